// round 1
// baseline (speedup 1.0000x reference)
#include <cuda_runtime.h>
#include <math.h>

// ---------------- problem constants ----------------
#define BATCH 2
#define SEQ   2048
#define HIDN  2048
#define NH    32
#define NG    8
#define HD    64
#define KVD   512          // NG * HD
#define MROWS (BATCH*SEQ)  // 4096

// ---------------- scratch (device globals: allocation-free) ----------------
__device__ float g_q [MROWS * HIDN];  // 32 MB
__device__ float g_k [MROWS * KVD];   //  8 MB
__device__ float g_v [MROWS * KVD];   //  8 MB
__device__ float g_ao[MROWS * HIDN];  // 32 MB

// ===================== SGEMM: C = A @ W + bias =====================
// A: [M,K] row-major, W: [K,N] row-major, bias: [N], C: [M,N]
// Tile 128x128x8, 256 threads, 8x8 per thread.
#define BM 128
#define BN 128
#define BKC 8
#define TM 8
#define TN 8

__global__ __launch_bounds__(256) void sgemm_bias(
    const float* __restrict__ A, const float* __restrict__ W,
    const float* __restrict__ bias, float* __restrict__ C,
    int M, int N, int K)
{
    __shared__ float As[BKC][BM + 4];   // transposed A tile, padded
    __shared__ float Bs[BKC][BN];

    const int tid = threadIdx.x;
    const int tx  = tid & 15;          // 0..15 (N dir)
    const int ty  = tid >> 4;          // 0..15 (M dir)
    const int rowBase = blockIdx.y * BM;
    const int colBase = blockIdx.x * BN;

    // global load mapping
    const int aRow = tid >> 1;         // 0..127
    const int aCol = (tid & 1) * 4;    // 0 or 4
    const int bRow = tid >> 5;         // 0..7
    const int bCol = (tid & 31) * 4;   // 0..124

    const float* Aptr = A + (size_t)(rowBase + aRow) * K + aCol;
    const float* Wptr = W + (size_t)bRow * N + colBase + bCol;

    float acc[TM][TN];
    #pragma unroll
    for (int i = 0; i < TM; i++)
        #pragma unroll
        for (int j = 0; j < TN; j++) acc[i][j] = 0.f;

    for (int k0 = 0; k0 < K; k0 += BKC) {
        float4 a4 = *(const float4*)(Aptr + k0);
        As[aCol + 0][aRow] = a4.x;
        As[aCol + 1][aRow] = a4.y;
        As[aCol + 2][aRow] = a4.z;
        As[aCol + 3][aRow] = a4.w;
        *(float4*)&Bs[bRow][bCol] = *(const float4*)(Wptr + (size_t)k0 * N);
        __syncthreads();

        #pragma unroll
        for (int kk = 0; kk < BKC; kk++) {
            float ar[TM], br[TN];
            float4 t0 = *(float4*)&As[kk][ty * TM];
            float4 t1 = *(float4*)&As[kk][ty * TM + 4];
            ar[0]=t0.x; ar[1]=t0.y; ar[2]=t0.z; ar[3]=t0.w;
            ar[4]=t1.x; ar[5]=t1.y; ar[6]=t1.z; ar[7]=t1.w;
            float4 u0 = *(float4*)&Bs[kk][tx * TN];
            float4 u1 = *(float4*)&Bs[kk][tx * TN + 4];
            br[0]=u0.x; br[1]=u0.y; br[2]=u0.z; br[3]=u0.w;
            br[4]=u1.x; br[5]=u1.y; br[6]=u1.z; br[7]=u1.w;
            #pragma unroll
            for (int i = 0; i < TM; i++)
                #pragma unroll
                for (int j = 0; j < TN; j++)
                    acc[i][j] += ar[i] * br[j];
        }
        __syncthreads();
    }

    // epilogue with bias
    #pragma unroll
    for (int i = 0; i < TM; i++) {
        int r = rowBase + ty * TM + i;
        float* Crow = C + (size_t)r * N + colBase + tx * TN;
        const float* brow = bias + colBase + tx * TN;
        #pragma unroll
        for (int j = 0; j < TN; j += 4) {
            float4 o;
            o.x = acc[i][j + 0] + brow[j + 0];
            o.y = acc[i][j + 1] + brow[j + 1];
            o.z = acc[i][j + 2] + brow[j + 2];
            o.w = acc[i][j + 3] + brow[j + 3];
            *(float4*)(Crow + j) = o;
        }
    }
}

// ===================== Flash attention (fp32, online softmax) ===============
// Grid: (SEQ/64, NH, BATCH). 256 threads: 64 query rows x 4 threads (quad).
// Quad thread q4 owns score cols cc = 4c+q4 and out cols dd = (4j+q4)*4+e.
#define AQ  64
#define AKT 64
#define PADW 68   // padded row stride (floats) -> conflict-free quad access

__global__ __launch_bounds__(256) void attn_kernel(
    const float* __restrict__ Q, const float* __restrict__ Kt,
    const float* __restrict__ Vt, float* __restrict__ O)
{
    extern __shared__ float sm[];
    float* Qs = sm;                    // 64 x 68
    float* Ks = sm + AQ * PADW;        // 64 x 68
    float* Vs = sm + 2 * AQ * PADW;    // 64 x 68
    float* Ps = sm + 3 * AQ * PADW;    // 64 x 68

    const int qt = blockIdx.x;
    const int h  = blockIdx.y;
    const int b  = blockIdx.z;
    const int g  = h >> 2;             // NH/NG = 4 heads per group

    const int tid = threadIdx.x;
    const int r   = tid >> 2;          // query row 0..63
    const int q4  = tid & 3;           // quad lane

    // load Q tile (64 x 64) into smem
    {
        int row = b * SEQ + qt * AQ + r;
        const float* src = Q + (size_t)row * HIDN + h * HD + q4 * 16;
        float* dst = Qs + r * PADW + q4 * 16;
        #pragma unroll
        for (int i = 0; i < 4; i++)
            *(float4*)(dst + 4 * i) = *(const float4*)(src + 4 * i);
    }

    float4 acc4[4];
    #pragma unroll
    for (int i = 0; i < 4; i++) acc4[i] = make_float4(0.f, 0.f, 0.f, 0.f);
    float m = -INFINITY, l = 0.f;
    const float scale = 0.125f;        // 1/sqrt(64)

    for (int kt = 0; kt < SEQ / AKT; kt++) {
        __syncthreads();  // previous-iter PV readers done before overwrite
        // load K, V tiles
        {
            int row = b * SEQ + kt * AKT + r;
            const float* ksrc = Kt + (size_t)row * KVD + g * HD + q4 * 16;
            const float* vsrc = Vt + (size_t)row * KVD + g * HD + q4 * 16;
            float* kdst = Ks + r * PADW + q4 * 16;
            float* vdst = Vs + r * PADW + q4 * 16;
            #pragma unroll
            for (int i = 0; i < 4; i++) {
                *(float4*)(kdst + 4 * i) = *(const float4*)(ksrc + 4 * i);
                *(float4*)(vdst + 4 * i) = *(const float4*)(vsrc + 4 * i);
            }
        }
        __syncthreads();

        // scores: s[c] = q_row . k_{4c+q4}
        float s[16];
        #pragma unroll
        for (int c = 0; c < 16; c++) s[c] = 0.f;
        #pragma unroll
        for (int d4 = 0; d4 < 16; d4++) {
            float4 qv = *(float4*)(Qs + r * PADW + d4 * 4);
            #pragma unroll
            for (int c = 0; c < 16; c++) {
                float4 kv = *(float4*)(Ks + (4 * c + q4) * PADW + d4 * 4);
                s[c] += qv.x * kv.x + qv.y * kv.y + qv.z * kv.z + qv.w * kv.w;
            }
        }

        // online softmax (quad reduction over the 64 keys of the tile)
        float tmax = s[0];
        #pragma unroll
        for (int c = 1; c < 16; c++) tmax = fmaxf(tmax, s[c]);
        tmax = fmaxf(tmax, __shfl_xor_sync(0xffffffffu, tmax, 1));
        tmax = fmaxf(tmax, __shfl_xor_sync(0xffffffffu, tmax, 2));

        float mnew  = fmaxf(m, tmax * scale);
        float alpha = __expf(m - mnew);
        float lsum = 0.f;
        #pragma unroll
        for (int c = 0; c < 16; c++) {
            float p = __expf(s[c] * scale - mnew);
            s[c] = p;
            lsum += p;
        }
        lsum += __shfl_xor_sync(0xffffffffu, lsum, 1);
        lsum += __shfl_xor_sync(0xffffffffu, lsum, 2);
        l = l * alpha + lsum;
        m = mnew;
        #pragma unroll
        for (int i = 0; i < 4; i++) {
            acc4[i].x *= alpha; acc4[i].y *= alpha;
            acc4[i].z *= alpha; acc4[i].w *= alpha;
        }

        // publish probabilities
        #pragma unroll
        for (int c = 0; c < 16; c++) Ps[r * PADW + 4 * c + q4] = s[c];
        __syncthreads();

        // PV accumulate: acc[dd] += sum_cc P[r][cc] * V[cc][dd]
        #pragma unroll 8
        for (int cc = 0; cc < AKT; cc++) {
            float p = Ps[r * PADW + cc];
            #pragma unroll
            for (int jj = 0; jj < 4; jj++) {
                float4 vv = *(float4*)(Vs + cc * PADW + (4 * jj + q4) * 4);
                acc4[jj].x += p * vv.x;
                acc4[jj].y += p * vv.y;
                acc4[jj].z += p * vv.z;
                acc4[jj].w += p * vv.w;
            }
        }
    }

    // epilogue: normalize and store [B,S,HID] layout
    float inv = 1.f / l;
    int row = b * SEQ + qt * AQ + r;
    float* dst = O + (size_t)row * HIDN + h * HD;
    #pragma unroll
    for (int jj = 0; jj < 4; jj++) {
        float4 o;
        o.x = acc4[jj].x * inv;
        o.y = acc4[jj].y * inv;
        o.z = acc4[jj].z * inv;
        o.w = acc4[jj].w * inv;
        *(float4*)(dst + (4 * jj + q4) * 4) = o;
    }
}

// ===================== launch =====================
extern "C" void kernel_launch(void* const* d_in, const int* in_sizes, int n_in,
                              void* d_out, int out_size)
{
    const float* hidden = (const float*)d_in[0];
    const float* Wq = (const float*)d_in[1];
    const float* bq = (const float*)d_in[2];
    const float* Wk = (const float*)d_in[3];
    const float* bk = (const float*)d_in[4];
    const float* Wv = (const float*)d_in[5];
    const float* bv = (const float*)d_in[6];
    const float* Wo = (const float*)d_in[7];
    const float* bo = (const float*)d_in[8];
    float* out = (float*)d_out;

    float *qp, *kp, *vp, *aop;
    cudaGetSymbolAddress((void**)&qp,  g_q);
    cudaGetSymbolAddress((void**)&kp,  g_k);
    cudaGetSymbolAddress((void**)&vp,  g_v);
    cudaGetSymbolAddress((void**)&aop, g_ao);

    dim3 blk(256);

    // QKV projections
    sgemm_bias<<<dim3(HIDN / BN, MROWS / BM), blk>>>(hidden, Wq, bq, qp,
                                                     MROWS, HIDN, HIDN);
    sgemm_bias<<<dim3(KVD  / BN, MROWS / BM), blk>>>(hidden, Wk, bk, kp,
                                                     MROWS, KVD, HIDN);
    sgemm_bias<<<dim3(KVD  / BN, MROWS / BM), blk>>>(hidden, Wv, bv, vp,
                                                     MROWS, KVD, HIDN);

    // attention
    size_t smem = (size_t)4 * AQ * PADW * sizeof(float);  // 69632 B
    cudaFuncSetAttribute(attn_kernel,
                         cudaFuncAttributeMaxDynamicSharedMemorySize,
                         (int)smem);
    attn_kernel<<<dim3(SEQ / AQ, NH, BATCH), blk, smem>>>(qp, kp, vp, aop);

    // output projection -> d_out
    sgemm_bias<<<dim3(HIDN / BN, MROWS / BM), blk>>>(aop, Wo, bo, out,
                                                     MROWS, HIDN, HIDN);
}

// round 2
// speedup vs baseline: 2.5837x; 2.5837x over previous
#include <cuda_runtime.h>
#include <math.h>

// ---------------- problem constants ----------------
#define BATCH 2
#define SEQ   2048
#define HIDN  2048
#define NH    32
#define NG    8
#define HD    64
#define KVD   512
#define MROWS (BATCH*SEQ)  // 4096

// ---------------- scratch ----------------
__device__ float g_q [MROWS * HIDN];
__device__ float g_k [MROWS * KVD];
__device__ float g_v [MROWS * KVD];
__device__ float g_ao[MROWS * HIDN];

// ---------------- tf32 helpers ----------------
__device__ __forceinline__ unsigned f2tf(float x) {
    unsigned u;
    asm("cvt.rna.tf32.f32 %0, %1;" : "=r"(u) : "f"(x));
    return u;
}
__device__ __forceinline__ void mma8(float* c, const unsigned* a, const unsigned* b) {
    asm volatile(
        "mma.sync.aligned.m16n8k8.row.col.f32.tf32.tf32.f32 "
        "{%0,%1,%2,%3}, {%4,%5,%6,%7}, {%8,%9}, {%0,%1,%2,%3};"
        : "+f"(c[0]), "+f"(c[1]), "+f"(c[2]), "+f"(c[3])
        : "r"(a[0]), "r"(a[1]), "r"(a[2]), "r"(a[3]), "r"(b[0]), "r"(b[1]));
}

// ===================== GEMM: C = A @ W + bias  (2-term tf32) ================
// A [M,K] rm, W [K,N] rm. Block 128x128x32, 8 warps (warp grid 4m x 2n),
// warp tile 32x64 -> 2 m-tiles x 8 n-tiles of m16n8k8.
#define GBM 128
#define GBN 128
#define GBK 32
#define ASTR 44     // padded row stride for As[128][44] (16B aligned, conflict-free)
#define BSTR 136    // padded row stride for Bs[32][136]

__global__ __launch_bounds__(256) void gemm_tf32x2(
    const float* __restrict__ A, const float* __restrict__ W,
    const float* __restrict__ bias, float* __restrict__ C,
    int M, int N, int K)
{
    __shared__ float As[GBM * ASTR];
    __shared__ float Bs[GBK * BSTR];

    const int tid  = threadIdx.x;
    const int wid  = tid >> 5;
    const int lane = tid & 31;
    const int gid  = lane >> 2;
    const int tig  = lane & 3;
    const int wm   = wid >> 1;   // 0..3
    const int wn   = wid & 1;    // 0..1
    const int rowBase = blockIdx.y * GBM;
    const int colBase = blockIdx.x * GBN;

    float acc[2][8][4];
    #pragma unroll
    for (int mt = 0; mt < 2; mt++)
        #pragma unroll
        for (int nt = 0; nt < 8; nt++)
            #pragma unroll
            for (int e = 0; e < 4; e++) acc[mt][nt][e] = 0.f;

    for (int k0 = 0; k0 < K; k0 += GBK) {
        // ---- load A tile 128x32 ----
        #pragma unroll
        for (int p = 0; p < 4; p++) {
            int f = p * 256 + tid;          // 1024 float4
            int r = f >> 3;                 // 8 float4 per row
            int c = (f & 7) * 4;
            float4 v = *(const float4*)(A + (size_t)(rowBase + r) * K + k0 + c);
            *(float4*)&As[r * ASTR + c] = v;
        }
        // ---- load B tile 32x128 ----
        #pragma unroll
        for (int p = 0; p < 4; p++) {
            int f = p * 256 + tid;
            int r = f >> 5;                 // 32 float4 per row
            int c = (f & 31) * 4;
            float4 v = *(const float4*)(W + (size_t)(k0 + r) * N + colBase + c);
            *(float4*)&Bs[r * BSTR + c] = v;
        }
        __syncthreads();

        #pragma unroll
        for (int ks = 0; ks < 4; ks++) {
            const int kk = ks * 8;
            // A fragments (hi + lo) for both m-tiles
            unsigned ah[2][4], al[2][4];
            #pragma unroll
            for (int mt = 0; mt < 2; mt++) {
                const int rb = wm * 32 + mt * 16 + gid;
                #pragma unroll
                for (int e = 0; e < 4; e++) {
                    int rr = rb + (e & 1) * 8;
                    int cc = kk + tig + (e >> 1) * 4;
                    float x = As[rr * ASTR + cc];
                    unsigned h = f2tf(x);
                    ah[mt][e] = h;
                    al[mt][e] = f2tf(x - __uint_as_float(h));
                }
            }
            #pragma unroll
            for (int nt = 0; nt < 8; nt++) {
                const int cb = wn * 64 + nt * 8 + gid;
                unsigned bh[2], bl[2];
                #pragma unroll
                for (int e = 0; e < 2; e++) {
                    float x = Bs[(kk + tig + e * 4) * BSTR + cb];
                    unsigned h = f2tf(x);
                    bh[e] = h;
                    bl[e] = f2tf(x - __uint_as_float(h));
                }
                #pragma unroll
                for (int mt = 0; mt < 2; mt++) {
                    mma8(acc[mt][nt], ah[mt], bh);
                    mma8(acc[mt][nt], al[mt], bh);
                    mma8(acc[mt][nt], ah[mt], bl);
                }
            }
        }
        __syncthreads();
    }

    // ---- epilogue + bias ----
    #pragma unroll
    for (int mt = 0; mt < 2; mt++) {
        int r0 = rowBase + wm * 32 + mt * 16 + gid;
        #pragma unroll
        for (int nt = 0; nt < 8; nt++) {
            int c = colBase + wn * 64 + nt * 8 + tig * 2;
            float2 bb = *(const float2*)(bias + c);
            float2 o0 = make_float2(acc[mt][nt][0] + bb.x, acc[mt][nt][1] + bb.y);
            float2 o1 = make_float2(acc[mt][nt][2] + bb.x, acc[mt][nt][3] + bb.y);
            *(float2*)(C + (size_t)r0 * N + c)       = o0;
            *(float2*)(C + (size_t)(r0 + 8) * N + c) = o1;
        }
    }
}

// ===================== Flash attention (tf32 MMA) ============================
// Block: 128 queries, 8 warps, each warp owns 16 query rows (full key width).
// Key tile 64. Warp work: scores 16x64 (1m x 8n), PV out 16x64 (1m x 8n).
#define AQR  128
#define AKT  64
#define QSTR 76     // padded row stride (16B aligned + conflict-free frags)

__global__ __launch_bounds__(256) void attn_mma(
    const float* __restrict__ Q, const float* __restrict__ Kt,
    const float* __restrict__ Vt, float* __restrict__ O)
{
    extern __shared__ float sm[];
    float* Qs = sm;                        // 128 x 76
    float* Ks = Qs + AQR * QSTR;           // 64 x 76
    float* Vs = Ks + AKT * QSTR;           // 64 x 76
    float* Ps = Vs + AKT * QSTR;           // 128 x 76

    const int qt = blockIdx.x, h = blockIdx.y, b = blockIdx.z;
    const int g  = h >> 2;                 // 4 heads per KV group
    const int tid  = threadIdx.x;
    const int wid  = tid >> 5;
    const int lane = tid & 31;
    const int gid  = lane >> 2;
    const int tig  = lane & 3;
    const int m0row = wid * 16;
    const float scale = 0.125f;            // 1/sqrt(64)

    // ---- load Q tile 128x64 (pre-scaled + tf32-rounded) ----
    #pragma unroll
    for (int p = 0; p < 8; p++) {
        int f = p * 256 + tid;             // 2048 float4
        int r = f >> 4;
        int c = (f & 15) * 4;
        float4 v = *(const float4*)(Q + (size_t)(b * SEQ + qt * AQR + r) * HIDN + h * HD + c);
        v.x = __uint_as_float(f2tf(v.x * scale));
        v.y = __uint_as_float(f2tf(v.y * scale));
        v.z = __uint_as_float(f2tf(v.z * scale));
        v.w = __uint_as_float(f2tf(v.w * scale));
        *(float4*)&Qs[r * QSTR + c] = v;
    }

    float o[8][4];
    #pragma unroll
    for (int nt = 0; nt < 8; nt++)
        #pragma unroll
        for (int e = 0; e < 4; e++) o[nt][e] = 0.f;
    float m0 = -INFINITY, m1 = -INFINITY, l0 = 0.f, l1 = 0.f;

    for (int kt = 0; kt < SEQ / AKT; kt++) {
        __syncthreads();   // prev-iter V readers done
        // ---- load K,V tiles 64x64 (tf32-rounded) ----
        #pragma unroll
        for (int p = 0; p < 4; p++) {
            int f = p * 256 + tid;         // 1024 float4
            int r = f >> 4;
            int c = (f & 15) * 4;
            size_t base = (size_t)(b * SEQ + kt * AKT + r) * KVD + g * HD + c;
            float4 kv = *(const float4*)(Kt + base);
            float4 vv = *(const float4*)(Vt + base);
            kv.x = __uint_as_float(f2tf(kv.x)); kv.y = __uint_as_float(f2tf(kv.y));
            kv.z = __uint_as_float(f2tf(kv.z)); kv.w = __uint_as_float(f2tf(kv.w));
            vv.x = __uint_as_float(f2tf(vv.x)); vv.y = __uint_as_float(f2tf(vv.y));
            vv.z = __uint_as_float(f2tf(vv.z)); vv.w = __uint_as_float(f2tf(vv.w));
            *(float4*)&Ks[r * QSTR + c] = kv;
            *(float4*)&Vs[r * QSTR + c] = vv;
        }
        __syncthreads();

        // ---- scores: S = Q @ K^T ----
        float sc[8][4];
        #pragma unroll
        for (int nt = 0; nt < 8; nt++)
            #pragma unroll
            for (int e = 0; e < 4; e++) sc[nt][e] = 0.f;

        #pragma unroll
        for (int ks = 0; ks < 8; ks++) {
            const int kk = ks * 8;
            unsigned a[4];
            a[0] = __float_as_uint(Qs[(m0row + gid)     * QSTR + kk + tig]);
            a[1] = __float_as_uint(Qs[(m0row + gid + 8) * QSTR + kk + tig]);
            a[2] = __float_as_uint(Qs[(m0row + gid)     * QSTR + kk + tig + 4]);
            a[3] = __float_as_uint(Qs[(m0row + gid + 8) * QSTR + kk + tig + 4]);
            #pragma unroll
            for (int nt = 0; nt < 8; nt++) {
                unsigned bf[2];
                bf[0] = __float_as_uint(Ks[(nt * 8 + gid) * QSTR + kk + tig]);
                bf[1] = __float_as_uint(Ks[(nt * 8 + gid) * QSTR + kk + tig + 4]);
                mma8(sc[nt], a, bf);
            }
        }

        // ---- online softmax (rows gid / gid+8 of this warp's tile) ----
        float mx0 = -INFINITY, mx1 = -INFINITY;
        #pragma unroll
        for (int nt = 0; nt < 8; nt++) {
            mx0 = fmaxf(mx0, fmaxf(sc[nt][0], sc[nt][1]));
            mx1 = fmaxf(mx1, fmaxf(sc[nt][2], sc[nt][3]));
        }
        mx0 = fmaxf(mx0, __shfl_xor_sync(0xffffffffu, mx0, 1));
        mx0 = fmaxf(mx0, __shfl_xor_sync(0xffffffffu, mx0, 2));
        mx1 = fmaxf(mx1, __shfl_xor_sync(0xffffffffu, mx1, 1));
        mx1 = fmaxf(mx1, __shfl_xor_sync(0xffffffffu, mx1, 2));

        float mn0 = fmaxf(m0, mx0), mn1 = fmaxf(m1, mx1);
        float al0 = __expf(m0 - mn0), al1 = __expf(m1 - mn1);
        float s0 = 0.f, s1 = 0.f;
        #pragma unroll
        for (int nt = 0; nt < 8; nt++) {
            float p00 = __expf(sc[nt][0] - mn0);
            float p01 = __expf(sc[nt][1] - mn0);
            float p10 = __expf(sc[nt][2] - mn1);
            float p11 = __expf(sc[nt][3] - mn1);
            s0 += p00 + p01;
            s1 += p10 + p11;
            *(float2*)&Ps[(m0row + gid)     * QSTR + nt * 8 + tig * 2] =
                make_float2(__uint_as_float(f2tf(p00)), __uint_as_float(f2tf(p01)));
            *(float2*)&Ps[(m0row + gid + 8) * QSTR + nt * 8 + tig * 2] =
                make_float2(__uint_as_float(f2tf(p10)), __uint_as_float(f2tf(p11)));
        }
        s0 += __shfl_xor_sync(0xffffffffu, s0, 1);
        s0 += __shfl_xor_sync(0xffffffffu, s0, 2);
        s1 += __shfl_xor_sync(0xffffffffu, s1, 1);
        s1 += __shfl_xor_sync(0xffffffffu, s1, 2);
        l0 = l0 * al0 + s0;  m0 = mn0;
        l1 = l1 * al1 + s1;  m1 = mn1;
        #pragma unroll
        for (int nt = 0; nt < 8; nt++) {
            o[nt][0] *= al0; o[nt][1] *= al0;
            o[nt][2] *= al1; o[nt][3] *= al1;
        }
        __syncwarp();   // Ps rows are warp-private; warp-level visibility suffices

        // ---- PV: O += P @ V ----
        #pragma unroll
        for (int ks = 0; ks < 8; ks++) {
            const int kk = ks * 8;
            unsigned a[4];
            a[0] = __float_as_uint(Ps[(m0row + gid)     * QSTR + kk + tig]);
            a[1] = __float_as_uint(Ps[(m0row + gid + 8) * QSTR + kk + tig]);
            a[2] = __float_as_uint(Ps[(m0row + gid)     * QSTR + kk + tig + 4]);
            a[3] = __float_as_uint(Ps[(m0row + gid + 8) * QSTR + kk + tig + 4]);
            #pragma unroll
            for (int nt = 0; nt < 8; nt++) {
                unsigned bf[2];
                bf[0] = __float_as_uint(Vs[(kk + tig)     * QSTR + nt * 8 + gid]);
                bf[1] = __float_as_uint(Vs[(kk + tig + 4) * QSTR + nt * 8 + gid]);
                mma8(o[nt], a, bf);
            }
        }
    }

    // ---- epilogue: normalize, store [B,S,HID] ----
    float i0 = 1.f / l0, i1 = 1.f / l1;
    int r0 = b * SEQ + qt * AQR + m0row + gid;
    float* dst0 = O + (size_t)r0 * HIDN + h * HD;
    float* dst1 = dst0 + (size_t)8 * HIDN;
    #pragma unroll
    for (int nt = 0; nt < 8; nt++) {
        *(float2*)(dst0 + nt * 8 + tig * 2) = make_float2(o[nt][0] * i0, o[nt][1] * i0);
        *(float2*)(dst1 + nt * 8 + tig * 2) = make_float2(o[nt][2] * i1, o[nt][3] * i1);
    }
}

// ===================== launch =====================
extern "C" void kernel_launch(void* const* d_in, const int* in_sizes, int n_in,
                              void* d_out, int out_size)
{
    const float* hidden = (const float*)d_in[0];
    const float* Wq = (const float*)d_in[1];
    const float* bq = (const float*)d_in[2];
    const float* Wk = (const float*)d_in[3];
    const float* bk = (const float*)d_in[4];
    const float* Wv = (const float*)d_in[5];
    const float* bv = (const float*)d_in[6];
    const float* Wo = (const float*)d_in[7];
    const float* bo = (const float*)d_in[8];
    float* out = (float*)d_out;

    float *qp, *kp, *vp, *aop;
    cudaGetSymbolAddress((void**)&qp,  g_q);
    cudaGetSymbolAddress((void**)&kp,  g_k);
    cudaGetSymbolAddress((void**)&vp,  g_v);
    cudaGetSymbolAddress((void**)&aop, g_ao);

    dim3 blk(256);

    gemm_tf32x2<<<dim3(HIDN / GBN, MROWS / GBM), blk>>>(hidden, Wq, bq, qp,
                                                        MROWS, HIDN, HIDN);
    gemm_tf32x2<<<dim3(KVD  / GBN, MROWS / GBM), blk>>>(hidden, Wk, bk, kp,
                                                        MROWS, KVD, HIDN);
    gemm_tf32x2<<<dim3(KVD  / GBN, MROWS / GBM), blk>>>(hidden, Wv, bv, vp,
                                                        MROWS, KVD, HIDN);

    size_t smem = (size_t)(AQR * QSTR + 2 * AKT * QSTR + AQR * QSTR) * sizeof(float);
    cudaFuncSetAttribute(attn_mma,
                         cudaFuncAttributeMaxDynamicSharedMemorySize, (int)smem);
    attn_mma<<<dim3(SEQ / AQR, NH, BATCH), blk, smem>>>(qp, kp, vp, aop);

    gemm_tf32x2<<<dim3(HIDN / GBN, MROWS / GBM), blk>>>(aop, Wo, bo, out,
                                                        MROWS, HIDN, HIDN);
}

// round 3
// speedup vs baseline: 5.5814x; 2.1602x over previous
#include <cuda_runtime.h>
#include <cuda_fp16.h>
#include <math.h>

// ---------------- problem constants ----------------
#define BATCH 2
#define SEQ   2048
#define HIDN  2048
#define NH    32
#define NG    8
#define HD    64
#define KVD   512
#define MROWS (BATCH*SEQ)  // 4096

// ---------------- device-global scratch ----------------
__device__ __half g_hh [MROWS * HIDN];    // hidden hi
__device__ __half g_hl [MROWS * HIDN];    // hidden lo
__device__ __half g_wqh[HIDN * HIDN];     // Wq^T hi  [N][K]
__device__ __half g_wql[HIDN * HIDN];
__device__ __half g_wkh[KVD  * HIDN];
__device__ __half g_wkl[KVD  * HIDN];
__device__ __half g_wvh[KVD  * HIDN];
__device__ __half g_wvl[KVD  * HIDN];
__device__ __half g_woh[HIDN * HIDN];
__device__ __half g_wol[HIDN * HIDN];
__device__ __half g_q  [MROWS * HIDN];    // q (pre-scaled), fp16
__device__ __half g_k  [MROWS * KVD];
__device__ __half g_v  [MROWS * KVD];
__device__ __half g_aoh[MROWS * HIDN];    // attention out hi
__device__ __half g_aol[MROWS * HIDN];    // attention out lo

// ---------------- helpers ----------------
__device__ __forceinline__ unsigned sptr(const void* p) {
    return (unsigned)__cvta_generic_to_shared(p);
}
__device__ __forceinline__ void ldm_x4(unsigned* r, unsigned a) {
    asm volatile("ldmatrix.sync.aligned.m8n8.x4.shared.b16 {%0,%1,%2,%3}, [%4];"
        : "=r"(r[0]), "=r"(r[1]), "=r"(r[2]), "=r"(r[3]) : "r"(a));
}
__device__ __forceinline__ void ldm_x4_t(unsigned* r, unsigned a) {
    asm volatile("ldmatrix.sync.aligned.m8n8.x4.trans.shared.b16 {%0,%1,%2,%3}, [%4];"
        : "=r"(r[0]), "=r"(r[1]), "=r"(r[2]), "=r"(r[3]) : "r"(a));
}
__device__ __forceinline__ void mma16(float* c, const unsigned* a, const unsigned* b) {
    asm volatile(
        "mma.sync.aligned.m16n8k16.row.col.f32.f16.f16.f32 "
        "{%0,%1,%2,%3}, {%4,%5,%6,%7}, {%8,%9}, {%0,%1,%2,%3};"
        : "+f"(c[0]), "+f"(c[1]), "+f"(c[2]), "+f"(c[3])
        : "r"(a[0]), "r"(a[1]), "r"(a[2]), "r"(a[3]), "r"(b[0]), "r"(b[1]));
}
__device__ __forceinline__ unsigned packh2(float x, float y) {
    __half2 h = __floats2half2_rn(x, y);
    return *(unsigned*)&h;
}

// ===================== prep: fp32 -> fp16 hi/lo split ========================
__global__ __launch_bounds__(256) void split_hl(
    const float* __restrict__ x, __half* __restrict__ hi, __half* __restrict__ lo, int n4)
{
    int i = blockIdx.x * 256 + threadIdx.x;
    if (i >= n4) return;
    float4 v = ((const float4*)x)[i];
    __half h0 = __float2half_rn(v.x), h1 = __float2half_rn(v.y);
    __half h2 = __float2half_rn(v.z), h3 = __float2half_rn(v.w);
    __half l0 = __float2half_rn(v.x - __half2float(h0));
    __half l1 = __float2half_rn(v.y - __half2float(h1));
    __half l2 = __float2half_rn(v.z - __half2float(h2));
    __half l3 = __float2half_rn(v.w - __half2float(h3));
    ((__half2*)hi)[2*i]   = __halves2half2(h0, h1);
    ((__half2*)hi)[2*i+1] = __halves2half2(h2, h3);
    ((__half2*)lo)[2*i]   = __halves2half2(l0, l1);
    ((__half2*)lo)[2*i+1] = __halves2half2(l2, l3);
}

// ===================== prep: W[K][N] fp32 -> T[N][K] fp16 hi/lo ==============
__global__ __launch_bounds__(256) void transpose_split(
    const float* __restrict__ W, __half* __restrict__ Th, __half* __restrict__ Tl,
    int K, int N)
{
    __shared__ float t[32][33];
    const int n0 = blockIdx.x * 32, k0 = blockIdx.y * 32;
    const int tx = threadIdx.x & 31, ty = threadIdx.x >> 5;  // 32 x 8
    #pragma unroll
    for (int i = 0; i < 4; i++)
        t[ty + 8*i][tx] = W[(size_t)(k0 + ty + 8*i) * N + n0 + tx];
    __syncthreads();
    #pragma unroll
    for (int i = 0; i < 4; i++) {
        float x = t[tx][ty + 8*i];
        __half h = __float2half_rn(x);
        __half l = __float2half_rn(x - __half2float(h));
        size_t idx = (size_t)(n0 + ty + 8*i) * K + k0 + tx;
        Th[idx] = h;
        Tl[idx] = l;
    }
}

// ===================== GEMM: C = (A@W + bias)*scale  (3-term fp16) ===========
// A hi/lo [M][K] half, B hi/lo [N][K] half. Block 128x128x32, 8 warps (4m x 2n).
#define GBM 128
#define GBN 128
#define GBK 32
#define KSTRH 40    // halfs per smem row (32 + 8 pad), 80 B, 16B-aligned

template<bool HALF_OUT>
__global__ __launch_bounds__(256, 2) void gemm_fp16x3(
    const __half* __restrict__ Ah, const __half* __restrict__ Al,
    const __half* __restrict__ Bh, const __half* __restrict__ Bl,
    const float* __restrict__ bias, void* __restrict__ Cout,
    int M, int N, int K, float outscale)
{
    __shared__ __half As[2][GBM * KSTRH];
    __shared__ __half Bs[2][GBN * KSTRH];

    const int tid = threadIdx.x;
    const int wid = tid >> 5, lane = tid & 31;
    const int gid = lane >> 2, tig = lane & 3;
    const int wm = wid >> 1, wn = wid & 1;
    const int rowBase = blockIdx.y * GBM;
    const int colBase = blockIdx.x * GBN;

    float acc[2][8][4];
    #pragma unroll
    for (int mt = 0; mt < 2; mt++)
        #pragma unroll
        for (int nt = 0; nt < 8; nt++)
            #pragma unroll
            for (int e = 0; e < 4; e++) acc[mt][nt][e] = 0.f;

    // ldmatrix lane address components (constant over k-loop)
    const int aRow = wm * 32 + (lane & 15);
    const int aColSel = (lane >> 4) * 8;
    const int bRowSel = ((lane >> 4) & 1) * 8 + (lane & 7);
    const int bColSel = ((lane >> 3) & 1) * 8;

    for (int k0 = 0; k0 < K; k0 += GBK) {
        #pragma unroll
        for (int i = 0; i < 2; i++) {
            int f = i * 256 + tid;           // 512 16B vectors per tile
            int r = f >> 2, c = (f & 3) * 8;
            size_t ga = (size_t)(rowBase + r) * K + k0 + c;
            size_t gb = (size_t)(colBase + r) * K + k0 + c;
            *(uint4*)&As[0][r * KSTRH + c] = *(const uint4*)(Ah + ga);
            *(uint4*)&As[1][r * KSTRH + c] = *(const uint4*)(Al + ga);
            *(uint4*)&Bs[0][r * KSTRH + c] = *(const uint4*)(Bh + gb);
            *(uint4*)&Bs[1][r * KSTRH + c] = *(const uint4*)(Bl + gb);
        }
        __syncthreads();

        #pragma unroll
        for (int ks = 0; ks < 2; ks++) {
            const int kk = ks * 16;
            unsigned ah[2][4], al[2][4];
            #pragma unroll
            for (int mt = 0; mt < 2; mt++) {
                int off = (aRow + mt * 16) * KSTRH + kk + aColSel;
                ldm_x4(ah[mt], sptr(&As[0][off]));
                ldm_x4(al[mt], sptr(&As[1][off]));
            }
            #pragma unroll
            for (int np = 0; np < 4; np++) {
                int off = (wn * 64 + np * 16 + bRowSel) * KSTRH + kk + bColSel;
                unsigned bh[4], bl[4];
                ldm_x4(bh, sptr(&Bs[0][off]));
                ldm_x4(bl, sptr(&Bs[1][off]));
                #pragma unroll
                for (int mt = 0; mt < 2; mt++) {
                    mma16(acc[mt][np*2+0], ah[mt], bh + 0);
                    mma16(acc[mt][np*2+0], ah[mt], bl + 0);
                    mma16(acc[mt][np*2+0], al[mt], bh + 0);
                    mma16(acc[mt][np*2+1], ah[mt], bh + 2);
                    mma16(acc[mt][np*2+1], ah[mt], bl + 2);
                    mma16(acc[mt][np*2+1], al[mt], bh + 2);
                }
            }
        }
        __syncthreads();
    }

    // epilogue
    #pragma unroll
    for (int mt = 0; mt < 2; mt++) {
        int r0 = rowBase + wm * 32 + mt * 16 + gid;
        #pragma unroll
        for (int nt = 0; nt < 8; nt++) {
            int c = colBase + wn * 64 + nt * 8 + tig * 2;
            float2 bb = *(const float2*)(bias + c);
            float v0 = (acc[mt][nt][0] + bb.x) * outscale;
            float v1 = (acc[mt][nt][1] + bb.y) * outscale;
            float v2 = (acc[mt][nt][2] + bb.x) * outscale;
            float v3 = (acc[mt][nt][3] + bb.y) * outscale;
            if (HALF_OUT) {
                __half* C = (__half*)Cout;
                *(__half2*)(C + (size_t)r0 * N + c)       = __floats2half2_rn(v0, v1);
                *(__half2*)(C + (size_t)(r0 + 8) * N + c) = __floats2half2_rn(v2, v3);
            } else {
                float* C = (float*)Cout;
                *(float2*)(C + (size_t)r0 * N + c)       = make_float2(v0, v1);
                *(float2*)(C + (size_t)(r0 + 8) * N + c) = make_float2(v2, v3);
            }
        }
    }
}

// ===================== Flash attention (fp16 MMA, P in registers) ============
#define ATQ  128
#define AKT  64
#define KSTR 72    // halfs per smem row (64 + 8 pad), 144 B

__global__ __launch_bounds__(256, 2) void attn_fp16(
    const __half* __restrict__ Qh, const __half* __restrict__ Kh,
    const __half* __restrict__ Vh, __half* __restrict__ Oh, __half* __restrict__ Ol)
{
    __shared__ __half Ks[AKT * KSTR];
    __shared__ __half Vs[AKT * KSTR];

    const int qt = blockIdx.x, h = blockIdx.y, b = blockIdx.z;
    const int g = h >> 2;
    const int tid = threadIdx.x, wid = tid >> 5, lane = tid & 31;
    const int gid = lane >> 2, tig = lane & 3;
    const int qrow0 = qt * ATQ + wid * 16;

    // preload Q fragments into registers (reused for all key tiles)
    unsigned qf[4][4];
    {
        const __half* qb = Qh + (size_t)(b * SEQ + qrow0) * HIDN + h * HD;
        #pragma unroll
        for (int ks = 0; ks < 4; ks++)
            #pragma unroll
            for (int e = 0; e < 4; e++) {
                int rr = gid + (e & 1) * 8;
                int cc = ks * 16 + tig * 2 + (e >> 1) * 8;
                qf[ks][e] = *(const unsigned*)(qb + (size_t)rr * HIDN + cc);
            }
    }

    float o[8][4];
    #pragma unroll
    for (int nt = 0; nt < 8; nt++)
        #pragma unroll
        for (int e = 0; e < 4; e++) o[nt][e] = 0.f;
    float m0 = -INFINITY, m1 = -INFINITY, l0 = 0.f, l1 = 0.f;

    const int kRowSel = ((lane >> 4) & 1) * 8 + (lane & 7);
    const int kColSel = ((lane >> 3) & 1) * 8;
    const int vRowSel = ((lane >> 3) & 1) * 8 + (lane & 7);
    const int vColSel = ((lane >> 4) & 1) * 8;

    for (int kt = 0; kt < SEQ / AKT; kt++) {
        __syncthreads();
        #pragma unroll
        for (int i = 0; i < 2; i++) {
            int f = i * 256 + tid;          // 512 16B vectors
            int r = f >> 3, c = (f & 7) * 8;
            size_t gb = (size_t)(b * SEQ + kt * AKT + r) * KVD + g * HD + c;
            *(uint4*)&Ks[r * KSTR + c] = *(const uint4*)(Kh + gb);
            *(uint4*)&Vs[r * KSTR + c] = *(const uint4*)(Vh + gb);
        }
        __syncthreads();

        // ---- scores S = Q @ K^T (q pre-scaled) ----
        float sc[8][4];
        #pragma unroll
        for (int nt = 0; nt < 8; nt++)
            #pragma unroll
            for (int e = 0; e < 4; e++) sc[nt][e] = 0.f;
        #pragma unroll
        for (int ks = 0; ks < 4; ks++) {
            #pragma unroll
            for (int np = 0; np < 4; np++) {
                unsigned bb[4];
                ldm_x4(bb, sptr(&Ks[(np * 16 + kRowSel) * KSTR + ks * 16 + kColSel]));
                mma16(sc[np*2+0], qf[ks], bb + 0);
                mma16(sc[np*2+1], qf[ks], bb + 2);
            }
        }

        // ---- online softmax ----
        float mx0 = -INFINITY, mx1 = -INFINITY;
        #pragma unroll
        for (int nt = 0; nt < 8; nt++) {
            mx0 = fmaxf(mx0, fmaxf(sc[nt][0], sc[nt][1]));
            mx1 = fmaxf(mx1, fmaxf(sc[nt][2], sc[nt][3]));
        }
        mx0 = fmaxf(mx0, __shfl_xor_sync(0xffffffffu, mx0, 1));
        mx0 = fmaxf(mx0, __shfl_xor_sync(0xffffffffu, mx0, 2));
        mx1 = fmaxf(mx1, __shfl_xor_sync(0xffffffffu, mx1, 1));
        mx1 = fmaxf(mx1, __shfl_xor_sync(0xffffffffu, mx1, 2));

        float mn0 = fmaxf(m0, mx0), mn1 = fmaxf(m1, mx1);
        float al0 = __expf(m0 - mn0), al1 = __expf(m1 - mn1);
        unsigned pf[4][4];
        float s0 = 0.f, s1 = 0.f;
        #pragma unroll
        for (int nt = 0; nt < 8; nt++) {
            float p0 = __expf(sc[nt][0] - mn0);
            float p1 = __expf(sc[nt][1] - mn0);
            float p2 = __expf(sc[nt][2] - mn1);
            float p3 = __expf(sc[nt][3] - mn1);
            s0 += p0 + p1;  s1 += p2 + p3;
            int ks = nt >> 1, hiSel = (nt & 1) * 2;
            pf[ks][0 + hiSel] = packh2(p0, p1);
            pf[ks][1 + hiSel] = packh2(p2, p3);
        }
        s0 += __shfl_xor_sync(0xffffffffu, s0, 1);
        s0 += __shfl_xor_sync(0xffffffffu, s0, 2);
        s1 += __shfl_xor_sync(0xffffffffu, s1, 1);
        s1 += __shfl_xor_sync(0xffffffffu, s1, 2);
        l0 = l0 * al0 + s0;  m0 = mn0;
        l1 = l1 * al1 + s1;  m1 = mn1;
        #pragma unroll
        for (int nt = 0; nt < 8; nt++) {
            o[nt][0] *= al0; o[nt][1] *= al0;
            o[nt][2] *= al1; o[nt][3] *= al1;
        }

        // ---- O += P @ V (V consumed via ldmatrix.trans) ----
        #pragma unroll
        for (int ks = 0; ks < 4; ks++) {
            #pragma unroll
            for (int np = 0; np < 4; np++) {
                unsigned bb[4];
                ldm_x4_t(bb, sptr(&Vs[(ks * 16 + vRowSel) * KSTR + np * 16 + vColSel]));
                mma16(o[np*2+0], pf[ks], bb + 0);
                mma16(o[np*2+1], pf[ks], bb + 2);
            }
        }
    }

    // ---- epilogue: normalize, split hi/lo, store ----
    float i0 = 1.f / l0, i1 = 1.f / l1;
    size_t r0 = (size_t)(b * SEQ + qrow0 + gid);
    __half* d0h = Oh + r0 * HIDN + h * HD;
    __half* d0l = Ol + r0 * HIDN + h * HD;
    __half* d1h = d0h + (size_t)8 * HIDN;
    __half* d1l = d0l + (size_t)8 * HIDN;
    #pragma unroll
    for (int nt = 0; nt < 8; nt++) {
        int c = nt * 8 + tig * 2;
        float x0 = o[nt][0] * i0, y0 = o[nt][1] * i0;
        float x1 = o[nt][2] * i1, y1 = o[nt][3] * i1;
        __half hx0 = __float2half_rn(x0), hy0 = __float2half_rn(y0);
        __half hx1 = __float2half_rn(x1), hy1 = __float2half_rn(y1);
        *(__half2*)(d0h + c) = __halves2half2(hx0, hy0);
        *(__half2*)(d1h + c) = __halves2half2(hx1, hy1);
        *(__half2*)(d0l + c) = __halves2half2(
            __float2half_rn(x0 - __half2float(hx0)), __float2half_rn(y0 - __half2float(hy0)));
        *(__half2*)(d1l + c) = __halves2half2(
            __float2half_rn(x1 - __half2float(hx1)), __float2half_rn(y1 - __half2float(hy1)));
    }
}

// ===================== launch =====================
extern "C" void kernel_launch(void* const* d_in, const int* in_sizes, int n_in,
                              void* d_out, int out_size)
{
    const float* hidden = (const float*)d_in[0];
    const float* Wq = (const float*)d_in[1];
    const float* bq = (const float*)d_in[2];
    const float* Wk = (const float*)d_in[3];
    const float* bk = (const float*)d_in[4];
    const float* Wv = (const float*)d_in[5];
    const float* bv = (const float*)d_in[6];
    const float* Wo = (const float*)d_in[7];
    const float* bo = (const float*)d_in[8];
    float* out = (float*)d_out;

    __half *hh, *hl, *wqh, *wql, *wkh, *wkl, *wvh, *wvl, *woh, *wol;
    __half *qp, *kp, *vp, *aoh, *aol;
    cudaGetSymbolAddress((void**)&hh,  g_hh);
    cudaGetSymbolAddress((void**)&hl,  g_hl);
    cudaGetSymbolAddress((void**)&wqh, g_wqh);
    cudaGetSymbolAddress((void**)&wql, g_wql);
    cudaGetSymbolAddress((void**)&wkh, g_wkh);
    cudaGetSymbolAddress((void**)&wkl, g_wkl);
    cudaGetSymbolAddress((void**)&wvh, g_wvh);
    cudaGetSymbolAddress((void**)&wvl, g_wvl);
    cudaGetSymbolAddress((void**)&woh, g_woh);
    cudaGetSymbolAddress((void**)&wol, g_wol);
    cudaGetSymbolAddress((void**)&qp,  g_q);
    cudaGetSymbolAddress((void**)&kp,  g_k);
    cudaGetSymbolAddress((void**)&vp,  g_v);
    cudaGetSymbolAddress((void**)&aoh, g_aoh);
    cudaGetSymbolAddress((void**)&aol, g_aol);

    // ---- prep ----
    split_hl<<<(MROWS * HIDN / 4 + 255) / 256, 256>>>(hidden, hh, hl, MROWS * HIDN / 4);
    transpose_split<<<dim3(HIDN / 32, HIDN / 32), 256>>>(Wq, wqh, wql, HIDN, HIDN);
    transpose_split<<<dim3(KVD  / 32, HIDN / 32), 256>>>(Wk, wkh, wkl, HIDN, KVD);
    transpose_split<<<dim3(KVD  / 32, HIDN / 32), 256>>>(Wv, wvh, wvl, HIDN, KVD);
    transpose_split<<<dim3(HIDN / 32, HIDN / 32), 256>>>(Wo, woh, wol, HIDN, HIDN);

    // ---- QKV projections (fp16 out; Q pre-scaled by 1/sqrt(HD)) ----
    gemm_fp16x3<true><<<dim3(HIDN / GBN, MROWS / GBM), 256>>>(
        hh, hl, wqh, wql, bq, qp, MROWS, HIDN, HIDN, 0.125f);
    gemm_fp16x3<true><<<dim3(KVD / GBN, MROWS / GBM), 256>>>(
        hh, hl, wkh, wkl, bk, kp, MROWS, KVD, HIDN, 1.0f);
    gemm_fp16x3<true><<<dim3(KVD / GBN, MROWS / GBM), 256>>>(
        hh, hl, wvh, wvl, bv, vp, MROWS, KVD, HIDN, 1.0f);

    // ---- attention ----
    attn_fp16<<<dim3(SEQ / ATQ, NH, BATCH), 256>>>(qp, kp, vp, aoh, aol);

    // ---- output projection (fp32 out) ----
    gemm_fp16x3<false><<<dim3(HIDN / GBN, MROWS / GBM), 256>>>(
        aoh, aol, woh, wol, bo, out, MROWS, HIDN, HIDN, 1.0f);
}

// round 6
// speedup vs baseline: 6.9204x; 1.2399x over previous
#include <cuda_runtime.h>
#include <cuda_fp16.h>
#include <cstdint>
#include <math.h>

// ---------------- problem constants ----------------
#define BATCH 2
#define SEQ   2048
#define HIDN  2048
#define NH    32
#define NG    8
#define HD    64
#define KVD   512
#define MROWS (BATCH*SEQ)  // 4096

// ---------------- device-global scratch ----------------
__device__ __half g_hh [MROWS * HIDN];
__device__ __half g_hl [MROWS * HIDN];
__device__ __half g_wqh[HIDN * HIDN];
__device__ __half g_wql[HIDN * HIDN];
__device__ __half g_wkh[KVD  * HIDN];
__device__ __half g_wkl[KVD  * HIDN];
__device__ __half g_wvh[KVD  * HIDN];
__device__ __half g_wvl[KVD  * HIDN];
__device__ __half g_woh[HIDN * HIDN];
__device__ __half g_wol[HIDN * HIDN];
__device__ __half g_q  [MROWS * HIDN];
__device__ __half g_k  [MROWS * KVD];
__device__ __half g_v  [MROWS * KVD];
__device__ __half g_aoh[MROWS * HIDN];
__device__ __half g_aol[MROWS * HIDN];

// ---------------- helpers ----------------
__device__ __forceinline__ unsigned sptr(const void* p) {
    return (unsigned)__cvta_generic_to_shared(p);
}
__device__ __forceinline__ void cpa16(unsigned dst, const void* src) {
    asm volatile("cp.async.cg.shared.global [%0], [%1], 16;"
        :: "r"(dst), "l"(src) : "memory");
}
__device__ __forceinline__ void cpa_commit() {
    asm volatile("cp.async.commit_group;" ::: "memory");
}
__device__ __forceinline__ void cpa_wait0() {
    asm volatile("cp.async.wait_group 0;" ::: "memory");
}
__device__ __forceinline__ void ldm_x4(unsigned* r, unsigned a) {
    asm volatile("ldmatrix.sync.aligned.m8n8.x4.shared.b16 {%0,%1,%2,%3}, [%4];"
        : "=r"(r[0]), "=r"(r[1]), "=r"(r[2]), "=r"(r[3]) : "r"(a));
}
__device__ __forceinline__ void ldm_x4_t(unsigned* r, unsigned a) {
    asm volatile("ldmatrix.sync.aligned.m8n8.x4.trans.shared.b16 {%0,%1,%2,%3}, [%4];"
        : "=r"(r[0]), "=r"(r[1]), "=r"(r[2]), "=r"(r[3]) : "r"(a));
}
__device__ __forceinline__ void mma16(float* c, const unsigned* a, const unsigned* b) {
    asm volatile(
        "mma.sync.aligned.m16n8k16.row.col.f32.f16.f16.f32 "
        "{%0,%1,%2,%3}, {%4,%5,%6,%7}, {%8,%9}, {%0,%1,%2,%3};"
        : "+f"(c[0]), "+f"(c[1]), "+f"(c[2]), "+f"(c[3])
        : "r"(a[0]), "r"(a[1]), "r"(a[2]), "r"(a[3]), "r"(b[0]), "r"(b[1]));
}
__device__ __forceinline__ unsigned packh2(float x, float y) {
    __half2 h = __floats2half2_rn(x, y);
    return *(unsigned*)&h;
}

// ===================== prep: fp32 -> fp16 hi/lo split ========================
__global__ __launch_bounds__(256) void split_hl(
    const float* __restrict__ x, __half* __restrict__ hi, __half* __restrict__ lo, int n4)
{
    int i = blockIdx.x * 256 + threadIdx.x;
    if (i >= n4) return;
    float4 v = ((const float4*)x)[i];
    __half h0 = __float2half_rn(v.x), h1 = __float2half_rn(v.y);
    __half h2 = __float2half_rn(v.z), h3 = __float2half_rn(v.w);
    __half l0 = __float2half_rn(v.x - __half2float(h0));
    __half l1 = __float2half_rn(v.y - __half2float(h1));
    __half l2 = __float2half_rn(v.z - __half2float(h2));
    __half l3 = __float2half_rn(v.w - __half2float(h3));
    ((__half2*)hi)[2*i]   = __halves2half2(h0, h1);
    ((__half2*)hi)[2*i+1] = __halves2half2(h2, h3);
    ((__half2*)lo)[2*i]   = __halves2half2(l0, l1);
    ((__half2*)lo)[2*i+1] = __halves2half2(l2, l3);
}

// ===================== prep: W[K][N] fp32 -> T[N][K] fp16 hi/lo ==============
__global__ __launch_bounds__(256) void transpose_split(
    const float* __restrict__ W, __half* __restrict__ Th, __half* __restrict__ Tl,
    int K, int N)
{
    __shared__ float t[32][33];
    const int n0 = blockIdx.x * 32, k0 = blockIdx.y * 32;
    const int tx = threadIdx.x & 31, ty = threadIdx.x >> 5;
    #pragma unroll
    for (int i = 0; i < 4; i++)
        t[ty + 8*i][tx] = W[(size_t)(k0 + ty + 8*i) * N + n0 + tx];
    __syncthreads();
    #pragma unroll
    for (int i = 0; i < 4; i++) {
        float x = t[tx][ty + 8*i];
        __half h = __float2half_rn(x);
        __half l = __float2half_rn(x - __half2float(h));
        size_t idx = (size_t)(n0 + ty + 8*i) * K + k0 + tx;
        Th[idx] = h;
        Tl[idx] = l;
    }
}

// ===================== GEMM: C = (A@W + bias)*scale, cp.async pipelined ======
// A hi/lo [M][K], B hi/lo [N][K]. Block 128x128x32, 8 warps (4m x 2n).
// TERMS=3: hh + al*bh + ah*bl ; TERMS=2: hh + al*bh (skips Bl entirely).
#define GBK   32
#define KSTRH 40                        // halfs per smem row (80 B)
#define MATH  (128 * KSTRH)             // halfs per matrix tile (5120)

template<int TERMS, bool HALF_OUT>
__global__ __launch_bounds__(256) void gemm_cp(
    const __half* __restrict__ Ah, const __half* __restrict__ Al,
    const __half* __restrict__ Bh, const __half* __restrict__ Bl,
    const float* __restrict__ bias, void* __restrict__ Cout,
    int N, int K, float outscale)
{
    constexpr int NMAT  = (TERMS == 3) ? 4 : 3;     // Ah, Al, Bh, [Bl]
    constexpr int STAGE = NMAT * MATH;              // halfs per stage
    extern __shared__ __half smh[];

    const int tid = threadIdx.x;
    const int wid = tid >> 5, lane = tid & 31;
    const int gid = lane >> 2, tig = lane & 3;
    const int wm = wid >> 1, wn = wid & 1;
    const int rowBase = blockIdx.y * 128;
    const int colBase = blockIdx.x * 128;

    float acc[2][8][4];
    #pragma unroll
    for (int mt = 0; mt < 2; mt++)
        #pragma unroll
        for (int nt = 0; nt < 8; nt++)
            #pragma unroll
            for (int e = 0; e < 4; e++) acc[mt][nt][e] = 0.f;

    const int aRow = wm * 32 + (lane & 15);
    const int aColSel = (lane >> 4) * 8;
    const int bRowSel = ((lane >> 4) & 1) * 8 + (lane & 7);
    const int bColSel = ((lane >> 3) & 1) * 8;

    // per-thread load mapping: 2 chunks of 16B per matrix
    const int lr0 = tid >> 2, lc0 = (tid & 3) * 8;          // rows 0..63
    const int lr1 = 64 + lr0;

    auto load_stage = [&](int kb, int ib) {
        unsigned base = sptr(smh) + (unsigned)(ib * STAGE) * 2;
        size_t ka = (size_t)(kb * GBK);
        // Ah, Al
        {
            size_t g0 = (size_t)(rowBase + lr0) * K + ka + lc0;
            size_t g1 = (size_t)(rowBase + lr1) * K + ka + lc0;
            unsigned s0 = base + (unsigned)(lr0 * KSTRH + lc0) * 2;
            unsigned s1 = base + (unsigned)(lr1 * KSTRH + lc0) * 2;
            cpa16(s0,            Ah + g0);
            cpa16(s1,            Ah + g1);
            cpa16(s0 + MATH * 2, Al + g0);
            cpa16(s1 + MATH * 2, Al + g1);
        }
        // Bh, [Bl]
        {
            size_t g0 = (size_t)(colBase + lr0) * K + ka + lc0;
            size_t g1 = (size_t)(colBase + lr1) * K + ka + lc0;
            unsigned s0 = base + (unsigned)(2 * MATH + lr0 * KSTRH + lc0) * 2;
            unsigned s1 = base + (unsigned)(2 * MATH + lr1 * KSTRH + lc0) * 2;
            cpa16(s0, Bh + g0);
            cpa16(s1, Bh + g1);
            if (TERMS == 3) {
                cpa16(s0 + MATH * 2, Bl + g0);
                cpa16(s1 + MATH * 2, Bl + g1);
            }
        }
    };

    const int kblocks = K / GBK;
    load_stage(0, 0);
    cpa_commit();

    for (int kb = 0; kb < kblocks; kb++) {
        const int ib = kb & 1;
        cpa_wait0();
        __syncthreads();
        if (kb + 1 < kblocks) {
            load_stage(kb + 1, ib ^ 1);
            cpa_commit();
        }

        const __half* As = smh + ib * STAGE;
        const __half* Bs = As + 2 * MATH;
        const __half* Bsl = Bs + MATH;

        #pragma unroll
        for (int ks = 0; ks < 2; ks++) {
            const int kk = ks * 16;
            unsigned ah[2][4], al[2][4];
            #pragma unroll
            for (int mt = 0; mt < 2; mt++) {
                int off = (aRow + mt * 16) * KSTRH + kk + aColSel;
                ldm_x4(ah[mt], sptr(As + off));
                ldm_x4(al[mt], sptr(As + MATH + off));
            }
            #pragma unroll
            for (int np = 0; np < 4; np++) {
                int off = (wn * 64 + np * 16 + bRowSel) * KSTRH + kk + bColSel;
                unsigned bh[4];
                ldm_x4(bh, sptr(Bs + off));
                unsigned bl[4];
                if (TERMS == 3) ldm_x4(bl, sptr(Bsl + off));
                #pragma unroll
                for (int mt = 0; mt < 2; mt++) {
                    mma16(acc[mt][np*2+0], ah[mt], bh + 0);
                    mma16(acc[mt][np*2+0], al[mt], bh + 0);
                    mma16(acc[mt][np*2+1], ah[mt], bh + 2);
                    mma16(acc[mt][np*2+1], al[mt], bh + 2);
                    if (TERMS == 3) {
                        mma16(acc[mt][np*2+0], ah[mt], bl + 0);
                        mma16(acc[mt][np*2+1], ah[mt], bl + 2);
                    }
                }
            }
        }
    }

    // epilogue
    #pragma unroll
    for (int mt = 0; mt < 2; mt++) {
        int r0 = rowBase + wm * 32 + mt * 16 + gid;
        #pragma unroll
        for (int nt = 0; nt < 8; nt++) {
            int c = colBase + wn * 64 + nt * 8 + tig * 2;
            float2 bb = *(const float2*)(bias + c);
            float v0 = (acc[mt][nt][0] + bb.x) * outscale;
            float v1 = (acc[mt][nt][1] + bb.y) * outscale;
            float v2 = (acc[mt][nt][2] + bb.x) * outscale;
            float v3 = (acc[mt][nt][3] + bb.y) * outscale;
            if (HALF_OUT) {
                __half* C = (__half*)Cout;
                *(__half2*)(C + (size_t)r0 * N + c)       = __floats2half2_rn(v0, v1);
                *(__half2*)(C + (size_t)(r0 + 8) * N + c) = __floats2half2_rn(v2, v3);
            } else {
                float* C = (float*)Cout;
                *(float2*)(C + (size_t)r0 * N + c)       = make_float2(v0, v1);
                *(float2*)(C + (size_t)(r0 + 8) * N + c) = make_float2(v2, v3);
            }
        }
    }
}

// ===================== Flash attention (fp16 MMA, cp.async K/V pipeline) =====
#define ATQ  128
#define AKT  64
#define KSTR 72

__global__ __launch_bounds__(256, 2) void attn_fp16(
    const __half* __restrict__ Qh, const __half* __restrict__ Kh,
    const __half* __restrict__ Vh, __half* __restrict__ Oh, __half* __restrict__ Ol)
{
    __shared__ __half Ks[2][AKT * KSTR];
    __shared__ __half Vs[2][AKT * KSTR];

    const int qt = blockIdx.x, h = blockIdx.y, b = blockIdx.z;
    const int g = h >> 2;
    const int tid = threadIdx.x, wid = tid >> 5, lane = tid & 31;
    const int gid = lane >> 2, tig = lane & 3;
    const int qrow0 = qt * ATQ + wid * 16;

    // per-thread K/V load mapping: 2 chunks per matrix per tile
    const int lr0 = tid >> 2, lc0 = (tid & 3) * 16;     // 4 chunks/row of 128B
    // rows 0..63 via two sub-chunks: (tid>>2) covers 64 rows, cols 0/16/32/48 halfs
    auto load_tile = [&](int kt, int ib) {
        #pragma unroll
        for (int i = 0; i < 2; i++) {
            int r = lr0;
            int c = lc0 + i * 8 * ((tid & 3) < 2 ? 0 : 0); // placeholder (unused)
            (void)c;
            int cc = (tid & 3) * 16 + i * 8;
            size_t gb = (size_t)(b * SEQ + kt * AKT + r) * KVD + g * HD + cc;
            unsigned sk = sptr(&Ks[ib][r * KSTR + cc]);
            unsigned sv = sptr(&Vs[ib][r * KSTR + cc]);
            cpa16(sk, Kh + gb);
            cpa16(sv, Vh + gb);
        }
    };

    unsigned qf[4][4];
    {
        const __half* qb = Qh + (size_t)(b * SEQ + qrow0) * HIDN + h * HD;
        #pragma unroll
        for (int ks = 0; ks < 4; ks++)
            #pragma unroll
            for (int e = 0; e < 4; e++) {
                int rr = gid + (e & 1) * 8;
                int cc = ks * 16 + tig * 2 + (e >> 1) * 8;
                qf[ks][e] = *(const unsigned*)(qb + (size_t)rr * HIDN + cc);
            }
    }

    load_tile(0, 0);
    cpa_commit();

    float o[8][4];
    #pragma unroll
    for (int nt = 0; nt < 8; nt++)
        #pragma unroll
        for (int e = 0; e < 4; e++) o[nt][e] = 0.f;
    float m0 = -INFINITY, m1 = -INFINITY, l0 = 0.f, l1 = 0.f;

    const int kRowSel = ((lane >> 4) & 1) * 8 + (lane & 7);
    const int kColSel = ((lane >> 3) & 1) * 8;
    const int vRowSel = ((lane >> 3) & 1) * 8 + (lane & 7);
    const int vColSel = ((lane >> 4) & 1) * 8;

    const int NT = SEQ / AKT;
    for (int kt = 0; kt < NT; kt++) {
        const int ib = kt & 1;
        cpa_wait0();
        __syncthreads();
        if (kt + 1 < NT) {
            load_tile(kt + 1, ib ^ 1);
            cpa_commit();
        }

        float sc[8][4];
        #pragma unroll
        for (int nt = 0; nt < 8; nt++)
            #pragma unroll
            for (int e = 0; e < 4; e++) sc[nt][e] = 0.f;
        #pragma unroll
        for (int ks = 0; ks < 4; ks++) {
            #pragma unroll
            for (int np = 0; np < 4; np++) {
                unsigned bb[4];
                ldm_x4(bb, sptr(&Ks[ib][(np * 16 + kRowSel) * KSTR + ks * 16 + kColSel]));
                mma16(sc[np*2+0], qf[ks], bb + 0);
                mma16(sc[np*2+1], qf[ks], bb + 2);
            }
        }

        float mx0 = -INFINITY, mx1 = -INFINITY;
        #pragma unroll
        for (int nt = 0; nt < 8; nt++) {
            mx0 = fmaxf(mx0, fmaxf(sc[nt][0], sc[nt][1]));
            mx1 = fmaxf(mx1, fmaxf(sc[nt][2], sc[nt][3]));
        }
        mx0 = fmaxf(mx0, __shfl_xor_sync(0xffffffffu, mx0, 1));
        mx0 = fmaxf(mx0, __shfl_xor_sync(0xffffffffu, mx0, 2));
        mx1 = fmaxf(mx1, __shfl_xor_sync(0xffffffffu, mx1, 1));
        mx1 = fmaxf(mx1, __shfl_xor_sync(0xffffffffu, mx1, 2));

        float mn0 = fmaxf(m0, mx0), mn1 = fmaxf(m1, mx1);
        float al0 = __expf(m0 - mn0), al1 = __expf(m1 - mn1);
        unsigned pf[4][4];
        float s0 = 0.f, s1 = 0.f;
        #pragma unroll
        for (int nt = 0; nt < 8; nt++) {
            float p0 = __expf(sc[nt][0] - mn0);
            float p1 = __expf(sc[nt][1] - mn0);
            float p2 = __expf(sc[nt][2] - mn1);
            float p3 = __expf(sc[nt][3] - mn1);
            s0 += p0 + p1;  s1 += p2 + p3;
            int ks = nt >> 1, hiSel = (nt & 1) * 2;
            pf[ks][0 + hiSel] = packh2(p0, p1);
            pf[ks][1 + hiSel] = packh2(p2, p3);
        }
        s0 += __shfl_xor_sync(0xffffffffu, s0, 1);
        s0 += __shfl_xor_sync(0xffffffffu, s0, 2);
        s1 += __shfl_xor_sync(0xffffffffu, s1, 1);
        s1 += __shfl_xor_sync(0xffffffffu, s1, 2);
        l0 = l0 * al0 + s0;  m0 = mn0;
        l1 = l1 * al1 + s1;  m1 = mn1;
        #pragma unroll
        for (int nt = 0; nt < 8; nt++) {
            o[nt][0] *= al0; o[nt][1] *= al0;
            o[nt][2] *= al1; o[nt][3] *= al1;
        }

        #pragma unroll
        for (int ks = 0; ks < 4; ks++) {
            #pragma unroll
            for (int np = 0; np < 4; np++) {
                unsigned bb[4];
                ldm_x4_t(bb, sptr(&Vs[ib][(ks * 16 + vRowSel) * KSTR + np * 16 + vColSel]));
                mma16(o[np*2+0], pf[ks], bb + 0);
                mma16(o[np*2+1], pf[ks], bb + 2);
            }
        }
    }

    float i0 = 1.f / l0, i1 = 1.f / l1;
    size_t r0 = (size_t)(b * SEQ + qrow0 + gid);
    __half* d0h = Oh + r0 * HIDN + h * HD;
    __half* d0l = Ol + r0 * HIDN + h * HD;
    __half* d1h = d0h + (size_t)8 * HIDN;
    __half* d1l = d0l + (size_t)8 * HIDN;
    #pragma unroll
    for (int nt = 0; nt < 8; nt++) {
        int c = nt * 8 + tig * 2;
        float x0 = o[nt][0] * i0, y0 = o[nt][1] * i0;
        float x1 = o[nt][2] * i1, y1 = o[nt][3] * i1;
        __half hx0 = __float2half_rn(x0), hy0 = __float2half_rn(y0);
        __half hx1 = __float2half_rn(x1), hy1 = __float2half_rn(y1);
        *(__half2*)(d0h + c) = __halves2half2(hx0, hy0);
        *(__half2*)(d1h + c) = __halves2half2(hx1, hy1);
        *(__half2*)(d0l + c) = __halves2half2(
            __float2half_rn(x0 - __half2float(hx0)), __float2half_rn(y0 - __half2float(hy0)));
        *(__half2*)(d1l + c) = __halves2half2(
            __float2half_rn(x1 - __half2float(hx1)), __float2half_rn(y1 - __half2float(hy1)));
    }
}

// ===================== launch =====================
extern "C" void kernel_launch(void* const* d_in, const int* in_sizes, int n_in,
                              void* d_out, int out_size)
{
    const float* hidden = (const float*)d_in[0];
    const float* Wq = (const float*)d_in[1];
    const float* bq = (const float*)d_in[2];
    const float* Wk = (const float*)d_in[3];
    const float* bk = (const float*)d_in[4];
    const float* Wv = (const float*)d_in[5];
    const float* bv = (const float*)d_in[6];
    const float* Wo = (const float*)d_in[7];
    const float* bo = (const float*)d_in[8];
    float* out = (float*)d_out;

    __half *hh, *hl, *wqh, *wql, *wkh, *wkl, *wvh, *wvl, *woh, *wol;
    __half *qp, *kp, *vp, *aoh, *aol;
    cudaGetSymbolAddress((void**)&hh,  g_hh);
    cudaGetSymbolAddress((void**)&hl,  g_hl);
    cudaGetSymbolAddress((void**)&wqh, g_wqh);
    cudaGetSymbolAddress((void**)&wql, g_wql);
    cudaGetSymbolAddress((void**)&wkh, g_wkh);
    cudaGetSymbolAddress((void**)&wkl, g_wkl);
    cudaGetSymbolAddress((void**)&wvh, g_wvh);
    cudaGetSymbolAddress((void**)&wvl, g_wvl);
    cudaGetSymbolAddress((void**)&woh, g_woh);
    cudaGetSymbolAddress((void**)&wol, g_wol);
    cudaGetSymbolAddress((void**)&qp,  g_q);
    cudaGetSymbolAddress((void**)&kp,  g_k);
    cudaGetSymbolAddress((void**)&vp,  g_v);
    cudaGetSymbolAddress((void**)&aoh, g_aoh);
    cudaGetSymbolAddress((void**)&aol, g_aol);

    // ---- prep ----
    split_hl<<<(MROWS * HIDN / 4 + 255) / 256, 256>>>(hidden, hh, hl, MROWS * HIDN / 4);
    transpose_split<<<dim3(HIDN / 32, HIDN / 32), 256>>>(Wq, wqh, wql, HIDN, HIDN);
    transpose_split<<<dim3(KVD  / 32, HIDN / 32), 256>>>(Wk, wkh, wkl, HIDN, KVD);
    transpose_split<<<dim3(KVD  / 32, HIDN / 32), 256>>>(Wv, wvh, wvl, HIDN, KVD);
    transpose_split<<<dim3(HIDN / 32, HIDN / 32), 256>>>(Wo, woh, wol, HIDN, HIDN);

    // ---- projections ----
    const int smem2 = 2 * 3 * MATH * sizeof(__half);   // 61440
    const int smem3 = 2 * 4 * MATH * sizeof(__half);   // 81920
    cudaFuncSetAttribute(gemm_cp<2, true>,
        cudaFuncAttributeMaxDynamicSharedMemorySize, smem2);
    cudaFuncSetAttribute(gemm_cp<3, false>,
        cudaFuncAttributeMaxDynamicSharedMemorySize, smem3);

    gemm_cp<2, true><<<dim3(HIDN / 128, MROWS / 128), 256, smem2>>>(
        hh, hl, wqh, wql, bq, qp, HIDN, HIDN, 0.125f);
    gemm_cp<2, true><<<dim3(KVD / 128, MROWS / 128), 256, smem2>>>(
        hh, hl, wkh, wkl, bk, kp, KVD, HIDN, 1.0f);
    gemm_cp<2, true><<<dim3(KVD / 128, MROWS / 128), 256, smem2>>>(
        hh, hl, wvh, wvl, bv, vp, KVD, HIDN, 1.0f);

    // ---- attention ----
    attn_fp16<<<dim3(SEQ / ATQ, NH, BATCH), 256>>>(qp, kp, vp, aoh, aol);

    // ---- output projection (3-term, fp32 out) ----
    gemm_cp<3, false><<<dim3(HIDN / 128, MROWS / 128), 256, smem3>>>(
        aoh, aol, woh, wol, bo, out, HIDN, HIDN, 1.0f);
}

// round 7
// speedup vs baseline: 7.1774x; 1.0371x over previous
#include <cuda_runtime.h>
#include <cuda_fp16.h>
#include <cstdint>
#include <math.h>

// ---------------- problem constants ----------------
#define BATCH 2
#define SEQ   2048
#define HIDN  2048
#define NH    32
#define NG    8
#define HD    64
#define KVD   512
#define QKVN  (HIDN + 2 * KVD)   // 3072 fused projection width
#define MROWS (BATCH*SEQ)        // 4096

// ---------------- device-global scratch ----------------
__device__ __half g_hh  [MROWS * HIDN];
__device__ __half g_hl  [MROWS * HIDN];
__device__ __half g_wxh [QKVN * HIDN];    // [Wq|Wk|Wv]^T hi  [N=3072][K=2048]
__device__ __half g_wxl [QKVN * HIDN];
__device__ __half g_woh [HIDN * HIDN];
__device__ __half g_wol [HIDN * HIDN];
__device__ float  g_bx  [QKVN];           // concat bias
__device__ __half g_qkv [MROWS * QKVN];   // fused q|k|v (q pre-scaled)
__device__ __half g_aoh [MROWS * HIDN];
__device__ __half g_aol [MROWS * HIDN];

// ---------------- helpers ----------------
__device__ __forceinline__ unsigned sptr(const void* p) {
    return (unsigned)__cvta_generic_to_shared(p);
}
__device__ __forceinline__ void cpa16(unsigned dst, const void* src) {
    asm volatile("cp.async.cg.shared.global [%0], [%1], 16;"
        :: "r"(dst), "l"(src) : "memory");
}
__device__ __forceinline__ void cpa_commit() {
    asm volatile("cp.async.commit_group;" ::: "memory");
}
__device__ __forceinline__ void cpa_wait0() {
    asm volatile("cp.async.wait_group 0;" ::: "memory");
}
__device__ __forceinline__ void ldm_x4(unsigned* r, unsigned a) {
    asm volatile("ldmatrix.sync.aligned.m8n8.x4.shared.b16 {%0,%1,%2,%3}, [%4];"
        : "=r"(r[0]), "=r"(r[1]), "=r"(r[2]), "=r"(r[3]) : "r"(a));
}
__device__ __forceinline__ void ldm_x4_t(unsigned* r, unsigned a) {
    asm volatile("ldmatrix.sync.aligned.m8n8.x4.trans.shared.b16 {%0,%1,%2,%3}, [%4];"
        : "=r"(r[0]), "=r"(r[1]), "=r"(r[2]), "=r"(r[3]) : "r"(a));
}
__device__ __forceinline__ void mma16(float* c, const unsigned* a, const unsigned* b) {
    asm volatile(
        "mma.sync.aligned.m16n8k16.row.col.f32.f16.f16.f32 "
        "{%0,%1,%2,%3}, {%4,%5,%6,%7}, {%8,%9}, {%0,%1,%2,%3};"
        : "+f"(c[0]), "+f"(c[1]), "+f"(c[2]), "+f"(c[3])
        : "r"(a[0]), "r"(a[1]), "r"(a[2]), "r"(a[3]), "r"(b[0]), "r"(b[1]));
}
__device__ __forceinline__ unsigned packh2(float x, float y) {
    __half2 h = __floats2half2_rn(x, y);
    return *(unsigned*)&h;
}

// ===================== prep: fp32 -> fp16 hi/lo split ========================
__global__ __launch_bounds__(256) void split_hl(
    const float* __restrict__ x, __half* __restrict__ hi, __half* __restrict__ lo, int n4)
{
    int i = blockIdx.x * 256 + threadIdx.x;
    if (i >= n4) return;
    float4 v = ((const float4*)x)[i];
    __half h0 = __float2half_rn(v.x), h1 = __float2half_rn(v.y);
    __half h2 = __float2half_rn(v.z), h3 = __float2half_rn(v.w);
    __half l0 = __float2half_rn(v.x - __half2float(h0));
    __half l1 = __float2half_rn(v.y - __half2float(h1));
    __half l2 = __float2half_rn(v.z - __half2float(h2));
    __half l3 = __float2half_rn(v.w - __half2float(h3));
    ((__half2*)hi)[2*i]   = __halves2half2(h0, h1);
    ((__half2*)hi)[2*i+1] = __halves2half2(h2, h3);
    ((__half2*)lo)[2*i]   = __halves2half2(l0, l1);
    ((__half2*)lo)[2*i+1] = __halves2half2(l2, l3);
}

// ===================== prep: fused [Wq|Wk|Wv] -> T[3072][2048] hi/lo =========
__global__ __launch_bounds__(256) void transpose_qkv(
    const float* __restrict__ Wq, const float* __restrict__ Wk,
    const float* __restrict__ Wv,
    __half* __restrict__ Th, __half* __restrict__ Tl)
{
    __shared__ float t[32][33];
    const int n0 = blockIdx.x * 32;            // fused col 0..3071
    const int k0 = blockIdx.y * 32;
    const int tx = threadIdx.x & 31, ty = threadIdx.x >> 5;

    const float* W;
    int nsrc, nwid;
    if (n0 < HIDN)            { W = Wq; nsrc = n0;               nwid = HIDN; }
    else if (n0 < HIDN + KVD) { W = Wk; nsrc = n0 - HIDN;        nwid = KVD;  }
    else                      { W = Wv; nsrc = n0 - HIDN - KVD;  nwid = KVD;  }

    #pragma unroll
    for (int i = 0; i < 4; i++)
        t[ty + 8*i][tx] = W[(size_t)(k0 + ty + 8*i) * nwid + nsrc + tx];
    __syncthreads();
    #pragma unroll
    for (int i = 0; i < 4; i++) {
        float x = t[tx][ty + 8*i];
        __half h = __float2half_rn(x);
        __half l = __float2half_rn(x - __half2float(h));
        size_t idx = (size_t)(n0 + ty + 8*i) * HIDN + k0 + tx;
        Th[idx] = h;
        Tl[idx] = l;
    }
}

// ===================== prep: Wo transpose ====================================
__global__ __launch_bounds__(256) void transpose_split(
    const float* __restrict__ W, __half* __restrict__ Th, __half* __restrict__ Tl,
    int K, int N)
{
    __shared__ float t[32][33];
    const int n0 = blockIdx.x * 32, k0 = blockIdx.y * 32;
    const int tx = threadIdx.x & 31, ty = threadIdx.x >> 5;
    #pragma unroll
    for (int i = 0; i < 4; i++)
        t[ty + 8*i][tx] = W[(size_t)(k0 + ty + 8*i) * N + n0 + tx];
    __syncthreads();
    #pragma unroll
    for (int i = 0; i < 4; i++) {
        float x = t[tx][ty + 8*i];
        __half h = __float2half_rn(x);
        __half l = __float2half_rn(x - __half2float(h));
        size_t idx = (size_t)(n0 + ty + 8*i) * K + k0 + tx;
        Th[idx] = h;
        Tl[idx] = l;
    }
}

// ===================== prep: concat bias =====================================
__global__ void bias_concat(const float* bq, const float* bk, const float* bv,
                            float* out)
{
    int i = blockIdx.x * 256 + threadIdx.x;
    if (i >= QKVN) return;
    out[i] = (i < HIDN) ? bq[i] : (i < HIDN + KVD ? bk[i - HIDN] : bv[i - HIDN - KVD]);
}

// ===================== GEMM: C = (A@W + bias)*colscale, cp.async pipelined ===
#define GBK   32
#define KSTRH 40
#define MATH  (128 * KSTRH)

template<int TERMS, bool HALF_OUT>
__global__ __launch_bounds__(256) void gemm_cp(
    const __half* __restrict__ Ah, const __half* __restrict__ Al,
    const __half* __restrict__ Bh, const __half* __restrict__ Bl,
    const float* __restrict__ bias, void* __restrict__ Cout,
    int N, int K, int qcols)           // cols < qcols get 0.125 scale
{
    constexpr int NMAT  = (TERMS == 3) ? 4 : 3;
    constexpr int STAGE = NMAT * MATH;
    extern __shared__ __half smh[];

    const int tid = threadIdx.x;
    const int wid = tid >> 5, lane = tid & 31;
    const int gid = lane >> 2, tig = lane & 3;
    const int wm = wid >> 1, wn = wid & 1;
    const int rowBase = blockIdx.y * 128;
    const int colBase = blockIdx.x * 128;

    float acc[2][8][4];
    #pragma unroll
    for (int mt = 0; mt < 2; mt++)
        #pragma unroll
        for (int nt = 0; nt < 8; nt++)
            #pragma unroll
            for (int e = 0; e < 4; e++) acc[mt][nt][e] = 0.f;

    const int aRow = wm * 32 + (lane & 15);
    const int aColSel = (lane >> 4) * 8;
    const int bRowSel = ((lane >> 4) & 1) * 8 + (lane & 7);
    const int bColSel = ((lane >> 3) & 1) * 8;

    const int lr0 = tid >> 2, lc0 = (tid & 3) * 8;
    const int lr1 = 64 + lr0;

    auto load_stage = [&](int kb, int ib) {
        unsigned base = sptr(smh) + (unsigned)(ib * STAGE) * 2;
        size_t ka = (size_t)(kb * GBK);
        {
            size_t g0 = (size_t)(rowBase + lr0) * K + ka + lc0;
            size_t g1 = (size_t)(rowBase + lr1) * K + ka + lc0;
            unsigned s0 = base + (unsigned)(lr0 * KSTRH + lc0) * 2;
            unsigned s1 = base + (unsigned)(lr1 * KSTRH + lc0) * 2;
            cpa16(s0,            Ah + g0);
            cpa16(s1,            Ah + g1);
            cpa16(s0 + MATH * 2, Al + g0);
            cpa16(s1 + MATH * 2, Al + g1);
        }
        {
            size_t g0 = (size_t)(colBase + lr0) * K + ka + lc0;
            size_t g1 = (size_t)(colBase + lr1) * K + ka + lc0;
            unsigned s0 = base + (unsigned)(2 * MATH + lr0 * KSTRH + lc0) * 2;
            unsigned s1 = base + (unsigned)(2 * MATH + lr1 * KSTRH + lc0) * 2;
            cpa16(s0, Bh + g0);
            cpa16(s1, Bh + g1);
            if (TERMS == 3) {
                cpa16(s0 + MATH * 2, Bl + g0);
                cpa16(s1 + MATH * 2, Bl + g1);
            }
        }
    };

    const int kblocks = K / GBK;
    load_stage(0, 0);
    cpa_commit();

    for (int kb = 0; kb < kblocks; kb++) {
        const int ib = kb & 1;
        cpa_wait0();
        __syncthreads();
        if (kb + 1 < kblocks) {
            load_stage(kb + 1, ib ^ 1);
            cpa_commit();
        }

        const __half* As = smh + ib * STAGE;
        const __half* Bs = As + 2 * MATH;
        const __half* Bsl = Bs + MATH;

        #pragma unroll
        for (int ks = 0; ks < 2; ks++) {
            const int kk = ks * 16;
            unsigned ah[2][4], al[2][4];
            #pragma unroll
            for (int mt = 0; mt < 2; mt++) {
                int off = (aRow + mt * 16) * KSTRH + kk + aColSel;
                ldm_x4(ah[mt], sptr(As + off));
                ldm_x4(al[mt], sptr(As + MATH + off));
            }
            #pragma unroll
            for (int np = 0; np < 4; np++) {
                int off = (wn * 64 + np * 16 + bRowSel) * KSTRH + kk + bColSel;
                unsigned bh[4];
                ldm_x4(bh, sptr(Bs + off));
                unsigned bl[4];
                if (TERMS == 3) ldm_x4(bl, sptr(Bsl + off));
                #pragma unroll
                for (int mt = 0; mt < 2; mt++) {
                    mma16(acc[mt][np*2+0], ah[mt], bh + 0);
                    mma16(acc[mt][np*2+0], al[mt], bh + 0);
                    mma16(acc[mt][np*2+1], ah[mt], bh + 2);
                    mma16(acc[mt][np*2+1], al[mt], bh + 2);
                    if (TERMS == 3) {
                        mma16(acc[mt][np*2+0], ah[mt], bl + 0);
                        mma16(acc[mt][np*2+1], ah[mt], bl + 2);
                    }
                }
            }
        }
    }

    #pragma unroll
    for (int mt = 0; mt < 2; mt++) {
        int r0 = rowBase + wm * 32 + mt * 16 + gid;
        #pragma unroll
        for (int nt = 0; nt < 8; nt++) {
            int c = colBase + wn * 64 + nt * 8 + tig * 2;
            float sc = (c < qcols) ? 0.125f : 1.0f;
            float2 bb = *(const float2*)(bias + c);
            float v0 = (acc[mt][nt][0] + bb.x) * sc;
            float v1 = (acc[mt][nt][1] + bb.y) * sc;
            float v2 = (acc[mt][nt][2] + bb.x) * sc;
            float v3 = (acc[mt][nt][3] + bb.y) * sc;
            if (HALF_OUT) {
                __half* C = (__half*)Cout;
                *(__half2*)(C + (size_t)r0 * N + c)       = __floats2half2_rn(v0, v1);
                *(__half2*)(C + (size_t)(r0 + 8) * N + c) = __floats2half2_rn(v2, v3);
            } else {
                float* C = (float*)Cout;
                *(float2*)(C + (size_t)r0 * N + c)       = make_float2(v0, v1);
                *(float2*)(C + (size_t)(r0 + 8) * N + c) = make_float2(v2, v3);
            }
        }
    }
}

// ===================== Flash attention (fp16 MMA, cp.async K/V pipeline) =====
#define ATQ  128
#define AKT  64
#define KSTR 72

__global__ __launch_bounds__(256, 2) void attn_fp16(
    const __half* __restrict__ QKV, __half* __restrict__ Oh, __half* __restrict__ Ol)
{
    __shared__ __half Ks[2][AKT * KSTR];
    __shared__ __half Vs[2][AKT * KSTR];

    const int qt = blockIdx.x, h = blockIdx.y, b = blockIdx.z;
    const int g = h >> 2;
    const int tid = threadIdx.x, wid = tid >> 5, lane = tid & 31;
    const int gid = lane >> 2, tig = lane & 3;
    const int qrow0 = qt * ATQ + wid * 16;

    const __half* Kbase = QKV + HIDN + (size_t)g * HD;
    const __half* Vbase = QKV + HIDN + KVD + (size_t)g * HD;

    const int lr0 = tid >> 2;
    auto load_tile = [&](int kt, int ib) {
        #pragma unroll
        for (int i = 0; i < 2; i++) {
            int r = lr0;
            int cc = (tid & 3) * 16 + i * 8;
            size_t gb = (size_t)(b * SEQ + kt * AKT + r) * QKVN + cc;
            cpa16(sptr(&Ks[ib][r * KSTR + cc]), Kbase + gb);
            cpa16(sptr(&Vs[ib][r * KSTR + cc]), Vbase + gb);
        }
    };

    unsigned qf[4][4];
    {
        const __half* qb = QKV + (size_t)(b * SEQ + qrow0) * QKVN + h * HD;
        #pragma unroll
        for (int ks = 0; ks < 4; ks++)
            #pragma unroll
            for (int e = 0; e < 4; e++) {
                int rr = gid + (e & 1) * 8;
                int cc = ks * 16 + tig * 2 + (e >> 1) * 8;
                qf[ks][e] = *(const unsigned*)(qb + (size_t)rr * QKVN + cc);
            }
    }

    load_tile(0, 0);
    cpa_commit();

    float o[8][4];
    #pragma unroll
    for (int nt = 0; nt < 8; nt++)
        #pragma unroll
        for (int e = 0; e < 4; e++) o[nt][e] = 0.f;
    float m0 = -INFINITY, m1 = -INFINITY, l0 = 0.f, l1 = 0.f;

    const int kRowSel = ((lane >> 4) & 1) * 8 + (lane & 7);
    const int kColSel = ((lane >> 3) & 1) * 8;
    const int vRowSel = ((lane >> 3) & 1) * 8 + (lane & 7);
    const int vColSel = ((lane >> 4) & 1) * 8;

    const int NT = SEQ / AKT;
    for (int kt = 0; kt < NT; kt++) {
        const int ib = kt & 1;
        cpa_wait0();
        __syncthreads();
        if (kt + 1 < NT) {
            load_tile(kt + 1, ib ^ 1);
            cpa_commit();
        }

        float sc[8][4];
        #pragma unroll
        for (int nt = 0; nt < 8; nt++)
            #pragma unroll
            for (int e = 0; e < 4; e++) sc[nt][e] = 0.f;
        #pragma unroll
        for (int ks = 0; ks < 4; ks++) {
            #pragma unroll
            for (int np = 0; np < 4; np++) {
                unsigned bb[4];
                ldm_x4(bb, sptr(&Ks[ib][(np * 16 + kRowSel) * KSTR + ks * 16 + kColSel]));
                mma16(sc[np*2+0], qf[ks], bb + 0);
                mma16(sc[np*2+1], qf[ks], bb + 2);
            }
        }

        float mx0 = -INFINITY, mx1 = -INFINITY;
        #pragma unroll
        for (int nt = 0; nt < 8; nt++) {
            mx0 = fmaxf(mx0, fmaxf(sc[nt][0], sc[nt][1]));
            mx1 = fmaxf(mx1, fmaxf(sc[nt][2], sc[nt][3]));
        }
        mx0 = fmaxf(mx0, __shfl_xor_sync(0xffffffffu, mx0, 1));
        mx0 = fmaxf(mx0, __shfl_xor_sync(0xffffffffu, mx0, 2));
        mx1 = fmaxf(mx1, __shfl_xor_sync(0xffffffffu, mx1, 1));
        mx1 = fmaxf(mx1, __shfl_xor_sync(0xffffffffu, mx1, 2));

        float mn0 = fmaxf(m0, mx0), mn1 = fmaxf(m1, mx1);
        float al0 = __expf(m0 - mn0), al1 = __expf(m1 - mn1);
        unsigned pf[4][4];
        float s0 = 0.f, s1 = 0.f;
        #pragma unroll
        for (int nt = 0; nt < 8; nt++) {
            float p0 = __expf(sc[nt][0] - mn0);
            float p1 = __expf(sc[nt][1] - mn0);
            float p2 = __expf(sc[nt][2] - mn1);
            float p3 = __expf(sc[nt][3] - mn1);
            s0 += p0 + p1;  s1 += p2 + p3;
            int ks = nt >> 1, hiSel = (nt & 1) * 2;
            pf[ks][0 + hiSel] = packh2(p0, p1);
            pf[ks][1 + hiSel] = packh2(p2, p3);
        }
        s0 += __shfl_xor_sync(0xffffffffu, s0, 1);
        s0 += __shfl_xor_sync(0xffffffffu, s0, 2);
        s1 += __shfl_xor_sync(0xffffffffu, s1, 1);
        s1 += __shfl_xor_sync(0xffffffffu, s1, 2);
        l0 = l0 * al0 + s0;  m0 = mn0;
        l1 = l1 * al1 + s1;  m1 = mn1;
        #pragma unroll
        for (int nt = 0; nt < 8; nt++) {
            o[nt][0] *= al0; o[nt][1] *= al0;
            o[nt][2] *= al1; o[nt][3] *= al1;
        }

        #pragma unroll
        for (int ks = 0; ks < 4; ks++) {
            #pragma unroll
            for (int np = 0; np < 4; np++) {
                unsigned bb[4];
                ldm_x4_t(bb, sptr(&Vs[ib][(ks * 16 + vRowSel) * KSTR + np * 16 + vColSel]));
                mma16(o[np*2+0], pf[ks], bb + 0);
                mma16(o[np*2+1], pf[ks], bb + 2);
            }
        }
    }

    float i0 = 1.f / l0, i1 = 1.f / l1;
    size_t r0 = (size_t)(b * SEQ + qrow0 + gid);
    __half* d0h = Oh + r0 * HIDN + h * HD;
    __half* d0l = Ol + r0 * HIDN + h * HD;
    __half* d1h = d0h + (size_t)8 * HIDN;
    __half* d1l = d0l + (size_t)8 * HIDN;
    #pragma unroll
    for (int nt = 0; nt < 8; nt++) {
        int c = nt * 8 + tig * 2;
        float x0 = o[nt][0] * i0, y0 = o[nt][1] * i0;
        float x1 = o[nt][2] * i1, y1 = o[nt][3] * i1;
        __half hx0 = __float2half_rn(x0), hy0 = __float2half_rn(y0);
        __half hx1 = __float2half_rn(x1), hy1 = __float2half_rn(y1);
        *(__half2*)(d0h + c) = __halves2half2(hx0, hy0);
        *(__half2*)(d1h + c) = __halves2half2(hx1, hy1);
        *(__half2*)(d0l + c) = __halves2half2(
            __float2half_rn(x0 - __half2float(hx0)), __float2half_rn(y0 - __half2float(hy0)));
        *(__half2*)(d1l + c) = __halves2half2(
            __float2half_rn(x1 - __half2float(hx1)), __float2half_rn(y1 - __half2float(hy1)));
    }
}

// ===================== launch =====================
extern "C" void kernel_launch(void* const* d_in, const int* in_sizes, int n_in,
                              void* d_out, int out_size)
{
    const float* hidden = (const float*)d_in[0];
    const float* Wq = (const float*)d_in[1];
    const float* bq = (const float*)d_in[2];
    const float* Wk = (const float*)d_in[3];
    const float* bk = (const float*)d_in[4];
    const float* Wv = (const float*)d_in[5];
    const float* bv = (const float*)d_in[6];
    const float* Wo = (const float*)d_in[7];
    const float* bo = (const float*)d_in[8];
    float* out = (float*)d_out;

    __half *hh, *hl, *wxh, *wxl, *woh, *wol, *qkv, *aoh, *aol;
    float* bx;
    cudaGetSymbolAddress((void**)&hh,  g_hh);
    cudaGetSymbolAddress((void**)&hl,  g_hl);
    cudaGetSymbolAddress((void**)&wxh, g_wxh);
    cudaGetSymbolAddress((void**)&wxl, g_wxl);
    cudaGetSymbolAddress((void**)&woh, g_woh);
    cudaGetSymbolAddress((void**)&wol, g_wol);
    cudaGetSymbolAddress((void**)&bx,  g_bx);
    cudaGetSymbolAddress((void**)&qkv, g_qkv);
    cudaGetSymbolAddress((void**)&aoh, g_aoh);
    cudaGetSymbolAddress((void**)&aol, g_aol);

    // ---- prep ----
    split_hl<<<(MROWS * HIDN / 4 + 255) / 256, 256>>>(hidden, hh, hl, MROWS * HIDN / 4);
    transpose_qkv<<<dim3(QKVN / 32, HIDN / 32), 256>>>(Wq, Wk, Wv, wxh, wxl);
    transpose_split<<<dim3(HIDN / 32, HIDN / 32), 256>>>(Wo, woh, wol, HIDN, HIDN);
    bias_concat<<<(QKVN + 255) / 256, 256>>>(bq, bk, bv, bx);

    // ---- fused QKV projection (2-term, fp16 out, Q cols scaled 0.125) ----
    const int smem2 = 2 * 3 * MATH * sizeof(__half);   // 61440
    const int smem3 = 2 * 4 * MATH * sizeof(__half);   // 81920
    cudaFuncSetAttribute(gemm_cp<2, true>,
        cudaFuncAttributeMaxDynamicSharedMemorySize, smem2);
    cudaFuncSetAttribute(gemm_cp<3, false>,
        cudaFuncAttributeMaxDynamicSharedMemorySize, smem3);

    gemm_cp<2, true><<<dim3(QKVN / 128, MROWS / 128), 256, smem2>>>(
        hh, hl, wxh, wxl, bx, qkv, QKVN, HIDN, HIDN);

    // ---- attention ----
    attn_fp16<<<dim3(SEQ / ATQ, NH, BATCH), 256>>>(qkv, aoh, aol);

    // ---- output projection (3-term, fp32 out) ----
    gemm_cp<3, false><<<dim3(HIDN / 128, MROWS / 128), 256, smem3>>>(
        aoh, aol, woh, wol, bo, out, HIDN, HIDN, 0);
}

// round 8
// speedup vs baseline: 8.3310x; 1.1607x over previous
#include <cuda_runtime.h>
#include <cuda_fp16.h>
#include <cstdint>
#include <math.h>

// ---------------- problem constants ----------------
#define BATCH 2
#define SEQ   2048
#define HIDN  2048
#define NH    32
#define NG    8
#define HD    64
#define KVD   512
#define QKVN  (HIDN + 2 * KVD)   // 3072
#define MROWS (BATCH*SEQ)        // 4096

// ---------------- device-global scratch ----------------
__device__ __half g_hh  [MROWS * HIDN];
__device__ __half g_hl  [MROWS * HIDN];
__device__ __half g_wxh [QKVN * HIDN];    // [Wq|Wk|Wv]^T hi  [N=3072][K=2048]
__device__ __half g_wxl [QKVN * HIDN];
__device__ __half g_woh [HIDN * HIDN];
__device__ float  g_bx  [QKVN];
__device__ __half g_qkv [MROWS * QKVN];   // fused q|k|v (q pre-scaled)
__device__ __half g_aoh [MROWS * HIDN];
__device__ __half g_aol [MROWS * HIDN];

// ---------------- helpers ----------------
__device__ __forceinline__ unsigned sptr(const void* p) {
    return (unsigned)__cvta_generic_to_shared(p);
}
__device__ __forceinline__ void cpa16(unsigned dst, const void* src) {
    asm volatile("cp.async.cg.shared.global [%0], [%1], 16;"
        :: "r"(dst), "l"(src) : "memory");
}
__device__ __forceinline__ void cpa_commit() {
    asm volatile("cp.async.commit_group;" ::: "memory");
}
__device__ __forceinline__ void cpa_wait0() {
    asm volatile("cp.async.wait_group 0;" ::: "memory");
}
__device__ __forceinline__ void ldm_x4(unsigned* r, unsigned a) {
    asm volatile("ldmatrix.sync.aligned.m8n8.x4.shared.b16 {%0,%1,%2,%3}, [%4];"
        : "=r"(r[0]), "=r"(r[1]), "=r"(r[2]), "=r"(r[3]) : "r"(a));
}
__device__ __forceinline__ void ldm_x4_t(unsigned* r, unsigned a) {
    asm volatile("ldmatrix.sync.aligned.m8n8.x4.trans.shared.b16 {%0,%1,%2,%3}, [%4];"
        : "=r"(r[0]), "=r"(r[1]), "=r"(r[2]), "=r"(r[3]) : "r"(a));
}
__device__ __forceinline__ void mma16(float* c, const unsigned* a, const unsigned* b) {
    asm volatile(
        "mma.sync.aligned.m16n8k16.row.col.f32.f16.f16.f32 "
        "{%0,%1,%2,%3}, {%4,%5,%6,%7}, {%8,%9}, {%0,%1,%2,%3};"
        : "+f"(c[0]), "+f"(c[1]), "+f"(c[2]), "+f"(c[3])
        : "r"(a[0]), "r"(a[1]), "r"(a[2]), "r"(a[3]), "r"(b[0]), "r"(b[1]));
}
__device__ __forceinline__ unsigned packh2(float x, float y) {
    __half2 h = __floats2half2_rn(x, y);
    return *(unsigned*)&h;
}

// ===================== prep: fp32 -> fp16 hi/lo split ========================
__global__ __launch_bounds__(256) void split_hl(
    const float* __restrict__ x, __half* __restrict__ hi, __half* __restrict__ lo, int n4)
{
    int i = blockIdx.x * 256 + threadIdx.x;
    if (i >= n4) return;
    float4 v = ((const float4*)x)[i];
    __half h0 = __float2half_rn(v.x), h1 = __float2half_rn(v.y);
    __half h2 = __float2half_rn(v.z), h3 = __float2half_rn(v.w);
    __half l0 = __float2half_rn(v.x - __half2float(h0));
    __half l1 = __float2half_rn(v.y - __half2float(h1));
    __half l2 = __float2half_rn(v.z - __half2float(h2));
    __half l3 = __float2half_rn(v.w - __half2float(h3));
    ((__half2*)hi)[2*i]   = __halves2half2(h0, h1);
    ((__half2*)hi)[2*i+1] = __halves2half2(h2, h3);
    ((__half2*)lo)[2*i]   = __halves2half2(l0, l1);
    ((__half2*)lo)[2*i+1] = __halves2half2(l2, l3);
}

// ===================== prep: fused [Wq|Wk|Wv] transpose + bias ===============
__global__ __launch_bounds__(256) void transpose_qkv(
    const float* __restrict__ Wq, const float* __restrict__ Wk,
    const float* __restrict__ Wv,
    const float* __restrict__ bq, const float* __restrict__ bk,
    const float* __restrict__ bv,
    __half* __restrict__ Th, __half* __restrict__ Tl, float* __restrict__ bx)
{
    __shared__ float t[32][33];
    const int n0 = blockIdx.x * 32;
    const int k0 = blockIdx.y * 32;
    const int tx = threadIdx.x & 31, ty = threadIdx.x >> 5;

    const float* W;
    const float* bsrc;
    int nsrc, nwid;
    if (n0 < HIDN)            { W = Wq; bsrc = bq; nsrc = n0;              nwid = HIDN; }
    else if (n0 < HIDN + KVD) { W = Wk; bsrc = bk; nsrc = n0 - HIDN;       nwid = KVD;  }
    else                      { W = Wv; bsrc = bv; nsrc = n0 - HIDN - KVD; nwid = KVD;  }

    if (blockIdx.y == 0 && ty == 0)
        bx[n0 + tx] = bsrc[nsrc + tx];

    #pragma unroll
    for (int i = 0; i < 4; i++)
        t[ty + 8*i][tx] = W[(size_t)(k0 + ty + 8*i) * nwid + nsrc + tx];
    __syncthreads();
    #pragma unroll
    for (int i = 0; i < 4; i++) {
        float x = t[tx][ty + 8*i];
        __half h = __float2half_rn(x);
        __half l = __float2half_rn(x - __half2float(h));
        size_t idx = (size_t)(n0 + ty + 8*i) * HIDN + k0 + tx;
        Th[idx] = h;
        Tl[idx] = l;
    }
}

// ===================== prep: Wo transpose (hi only) ==========================
__global__ __launch_bounds__(256) void transpose_hi(
    const float* __restrict__ W, __half* __restrict__ Th, int K, int N)
{
    __shared__ float t[32][33];
    const int n0 = blockIdx.x * 32, k0 = blockIdx.y * 32;
    const int tx = threadIdx.x & 31, ty = threadIdx.x >> 5;
    #pragma unroll
    for (int i = 0; i < 4; i++)
        t[ty + 8*i][tx] = W[(size_t)(k0 + ty + 8*i) * N + n0 + tx];
    __syncthreads();
    #pragma unroll
    for (int i = 0; i < 4; i++)
        Th[(size_t)(n0 + ty + 8*i) * K + k0 + tx] = __float2half_rn(t[tx][ty + 8*i]);
}

// ===================== GEMM: C = (Ah+Al)@Bh + bias, 2-term, GBK=64 ===========
#define GBK   64
#define KSTRH 72                         // 64 + 8 pad halves (144 B row)
#define MATH  (128 * KSTRH)              // 9216 halves per matrix tile
#define STAGE (3 * MATH)                 // Ah, Al, Bh

template<bool HALF_OUT>
__global__ __launch_bounds__(256) void gemm_cp(
    const __half* __restrict__ Ah, const __half* __restrict__ Al,
    const __half* __restrict__ Bh,
    const float* __restrict__ bias, void* __restrict__ Cout,
    int N, int K, int qcols)             // cols < qcols get 0.125 scale
{
    extern __shared__ __half smh[];

    const int tid = threadIdx.x;
    const int wid = tid >> 5, lane = tid & 31;
    const int gid = lane >> 2, tig = lane & 3;
    const int wm = wid >> 1, wn = wid & 1;
    const int rowBase = blockIdx.y * 128;
    const int colBase = blockIdx.x * 128;

    float acc[2][8][4];
    #pragma unroll
    for (int mt = 0; mt < 2; mt++)
        #pragma unroll
        for (int nt = 0; nt < 8; nt++)
            #pragma unroll
            for (int e = 0; e < 4; e++) acc[mt][nt][e] = 0.f;

    const int aRow = wm * 32 + (lane & 15);
    const int aColSel = (lane >> 4) * 8;
    const int bRowSel = ((lane >> 4) & 1) * 8 + (lane & 7);
    const int bColSel = ((lane >> 3) & 1) * 8;

    auto load_stage = [&](int kb, int ib) {
        unsigned base = sptr(smh) + (unsigned)(ib * STAGE) * 2;
        size_t ka = (size_t)kb * GBK;
        #pragma unroll
        for (int i = 0; i < 4; i++) {
            int f = i * 256 + tid;           // 1024 chunks per matrix
            int r = f >> 3, c = (f & 7) * 8;
            unsigned soff = base + (unsigned)(r * KSTRH + c) * 2;
            size_t ga = (size_t)(rowBase + r) * K + ka + c;
            size_t gb = (size_t)(colBase + r) * K + ka + c;
            cpa16(soff,                Ah + ga);
            cpa16(soff + MATH * 2,     Al + ga);
            cpa16(soff + 2 * MATH * 2, Bh + gb);
        }
    };

    const int kblocks = K / GBK;
    load_stage(0, 0);
    cpa_commit();

    for (int kb = 0; kb < kblocks; kb++) {
        const int ib = kb & 1;
        cpa_wait0();
        __syncthreads();
        if (kb + 1 < kblocks) {
            load_stage(kb + 1, ib ^ 1);
            cpa_commit();
        }

        const __half* As = smh + ib * STAGE;
        const __half* Bs = As + 2 * MATH;

        #pragma unroll
        for (int ks = 0; ks < 4; ks++) {
            const int kk = ks * 16;
            unsigned ah[2][4], al[2][4];
            #pragma unroll
            for (int mt = 0; mt < 2; mt++) {
                int off = (aRow + mt * 16) * KSTRH + kk + aColSel;
                ldm_x4(ah[mt], sptr(As + off));
                ldm_x4(al[mt], sptr(As + MATH + off));
            }
            #pragma unroll
            for (int np = 0; np < 4; np++) {
                int off = (wn * 64 + np * 16 + bRowSel) * KSTRH + kk + bColSel;
                unsigned bh[4];
                ldm_x4(bh, sptr(Bs + off));
                #pragma unroll
                for (int mt = 0; mt < 2; mt++) {
                    mma16(acc[mt][np*2+0], ah[mt], bh + 0);
                    mma16(acc[mt][np*2+0], al[mt], bh + 0);
                    mma16(acc[mt][np*2+1], ah[mt], bh + 2);
                    mma16(acc[mt][np*2+1], al[mt], bh + 2);
                }
            }
        }
    }

    #pragma unroll
    for (int mt = 0; mt < 2; mt++) {
        int r0 = rowBase + wm * 32 + mt * 16 + gid;
        #pragma unroll
        for (int nt = 0; nt < 8; nt++) {
            int c = colBase + wn * 64 + nt * 8 + tig * 2;
            float sc = (c < qcols) ? 0.125f : 1.0f;
            float2 bb = *(const float2*)(bias + c);
            float v0 = (acc[mt][nt][0] + bb.x) * sc;
            float v1 = (acc[mt][nt][1] + bb.y) * sc;
            float v2 = (acc[mt][nt][2] + bb.x) * sc;
            float v3 = (acc[mt][nt][3] + bb.y) * sc;
            if (HALF_OUT) {
                __half* C = (__half*)Cout;
                *(__half2*)(C + (size_t)r0 * N + c)       = __floats2half2_rn(v0, v1);
                *(__half2*)(C + (size_t)(r0 + 8) * N + c) = __floats2half2_rn(v2, v3);
            } else {
                float* C = (float*)Cout;
                *(float2*)(C + (size_t)r0 * N + c)       = make_float2(v0, v1);
                *(float2*)(C + (size_t)(r0 + 8) * N + c) = make_float2(v2, v3);
            }
        }
    }
}

// ===================== Flash attention (fp16 MMA, cp.async K/V pipeline) =====
#define ATQ  128
#define AKT  64
#define KSTR 72

__global__ __launch_bounds__(256, 2) void attn_fp16(
    const __half* __restrict__ QKV, __half* __restrict__ Oh, __half* __restrict__ Ol)
{
    __shared__ __half Ks[2][AKT * KSTR];
    __shared__ __half Vs[2][AKT * KSTR];

    const int qt = blockIdx.x, h = blockIdx.y, b = blockIdx.z;
    const int g = h >> 2;
    const int tid = threadIdx.x, wid = tid >> 5, lane = tid & 31;
    const int gid = lane >> 2, tig = lane & 3;
    const int qrow0 = qt * ATQ + wid * 16;

    const __half* Kbase = QKV + HIDN + (size_t)g * HD;
    const __half* Vbase = QKV + HIDN + KVD + (size_t)g * HD;

    const int lr0 = tid >> 2;
    auto load_tile = [&](int kt, int ib) {
        #pragma unroll
        for (int i = 0; i < 2; i++) {
            int r = lr0;
            int cc = (tid & 3) * 16 + i * 8;
            size_t gb = (size_t)(b * SEQ + kt * AKT + r) * QKVN + cc;
            cpa16(sptr(&Ks[ib][r * KSTR + cc]), Kbase + gb);
            cpa16(sptr(&Vs[ib][r * KSTR + cc]), Vbase + gb);
        }
    };

    unsigned qf[4][4];
    {
        const __half* qb = QKV + (size_t)(b * SEQ + qrow0) * QKVN + h * HD;
        #pragma unroll
        for (int ks = 0; ks < 4; ks++)
            #pragma unroll
            for (int e = 0; e < 4; e++) {
                int rr = gid + (e & 1) * 8;
                int cc = ks * 16 + tig * 2 + (e >> 1) * 8;
                qf[ks][e] = *(const unsigned*)(qb + (size_t)rr * QKVN + cc);
            }
    }

    load_tile(0, 0);
    cpa_commit();

    float o[8][4];
    #pragma unroll
    for (int nt = 0; nt < 8; nt++)
        #pragma unroll
        for (int e = 0; e < 4; e++) o[nt][e] = 0.f;
    float m0 = -INFINITY, m1 = -INFINITY, l0 = 0.f, l1 = 0.f;

    const int kRowSel = ((lane >> 4) & 1) * 8 + (lane & 7);
    const int kColSel = ((lane >> 3) & 1) * 8;
    const int vRowSel = ((lane >> 3) & 1) * 8 + (lane & 7);
    const int vColSel = ((lane >> 4) & 1) * 8;

    const int NT = SEQ / AKT;
    for (int kt = 0; kt < NT; kt++) {
        const int ib = kt & 1;
        cpa_wait0();
        __syncthreads();
        if (kt + 1 < NT) {
            load_tile(kt + 1, ib ^ 1);
            cpa_commit();
        }

        float sc[8][4];
        #pragma unroll
        for (int nt = 0; nt < 8; nt++)
            #pragma unroll
            for (int e = 0; e < 4; e++) sc[nt][e] = 0.f;
        #pragma unroll
        for (int ks = 0; ks < 4; ks++) {
            #pragma unroll
            for (int np = 0; np < 4; np++) {
                unsigned bb[4];
                ldm_x4(bb, sptr(&Ks[ib][(np * 16 + kRowSel) * KSTR + ks * 16 + kColSel]));
                mma16(sc[np*2+0], qf[ks], bb + 0);
                mma16(sc[np*2+1], qf[ks], bb + 2);
            }
        }

        float mx0 = -INFINITY, mx1 = -INFINITY;
        #pragma unroll
        for (int nt = 0; nt < 8; nt++) {
            mx0 = fmaxf(mx0, fmaxf(sc[nt][0], sc[nt][1]));
            mx1 = fmaxf(mx1, fmaxf(sc[nt][2], sc[nt][3]));
        }
        mx0 = fmaxf(mx0, __shfl_xor_sync(0xffffffffu, mx0, 1));
        mx0 = fmaxf(mx0, __shfl_xor_sync(0xffffffffu, mx0, 2));
        mx1 = fmaxf(mx1, __shfl_xor_sync(0xffffffffu, mx1, 1));
        mx1 = fmaxf(mx1, __shfl_xor_sync(0xffffffffu, mx1, 2));

        float mn0 = fmaxf(m0, mx0), mn1 = fmaxf(m1, mx1);
        float al0 = __expf(m0 - mn0), al1 = __expf(m1 - mn1);
        unsigned pf[4][4];
        float s0 = 0.f, s1 = 0.f;
        #pragma unroll
        for (int nt = 0; nt < 8; nt++) {
            float p0 = __expf(sc[nt][0] - mn0);
            float p1 = __expf(sc[nt][1] - mn0);
            float p2 = __expf(sc[nt][2] - mn1);
            float p3 = __expf(sc[nt][3] - mn1);
            s0 += p0 + p1;  s1 += p2 + p3;
            int ks = nt >> 1, hiSel = (nt & 1) * 2;
            pf[ks][0 + hiSel] = packh2(p0, p1);
            pf[ks][1 + hiSel] = packh2(p2, p3);
        }
        s0 += __shfl_xor_sync(0xffffffffu, s0, 1);
        s0 += __shfl_xor_sync(0xffffffffu, s0, 2);
        s1 += __shfl_xor_sync(0xffffffffu, s1, 1);
        s1 += __shfl_xor_sync(0xffffffffu, s1, 2);
        l0 = l0 * al0 + s0;  m0 = mn0;
        l1 = l1 * al1 + s1;  m1 = mn1;
        #pragma unroll
        for (int nt = 0; nt < 8; nt++) {
            o[nt][0] *= al0; o[nt][1] *= al0;
            o[nt][2] *= al1; o[nt][3] *= al1;
        }

        #pragma unroll
        for (int ks = 0; ks < 4; ks++) {
            #pragma unroll
            for (int np = 0; np < 4; np++) {
                unsigned bb[4];
                ldm_x4_t(bb, sptr(&Vs[ib][(ks * 16 + vRowSel) * KSTR + np * 16 + vColSel]));
                mma16(o[np*2+0], pf[ks], bb + 0);
                mma16(o[np*2+1], pf[ks], bb + 2);
            }
        }
    }

    float i0 = 1.f / l0, i1 = 1.f / l1;
    size_t r0 = (size_t)(b * SEQ + qrow0 + gid);
    __half* d0h = Oh + r0 * HIDN + h * HD;
    __half* d0l = Ol + r0 * HIDN + h * HD;
    __half* d1h = d0h + (size_t)8 * HIDN;
    __half* d1l = d0l + (size_t)8 * HIDN;
    #pragma unroll
    for (int nt = 0; nt < 8; nt++) {
        int c = nt * 8 + tig * 2;
        float x0 = o[nt][0] * i0, y0 = o[nt][1] * i0;
        float x1 = o[nt][2] * i1, y1 = o[nt][3] * i1;
        __half hx0 = __float2half_rn(x0), hy0 = __float2half_rn(y0);
        __half hx1 = __float2half_rn(x1), hy1 = __float2half_rn(y1);
        *(__half2*)(d0h + c) = __halves2half2(hx0, hy0);
        *(__half2*)(d1h + c) = __halves2half2(hx1, hy1);
        *(__half2*)(d0l + c) = __halves2half2(
            __float2half_rn(x0 - __half2float(hx0)), __float2half_rn(y0 - __half2float(hy0)));
        *(__half2*)(d1l + c) = __halves2half2(
            __float2half_rn(x1 - __half2float(hx1)), __float2half_rn(y1 - __half2float(hy1)));
    }
}

// ===================== launch =====================
extern "C" void kernel_launch(void* const* d_in, const int* in_sizes, int n_in,
                              void* d_out, int out_size)
{
    const float* hidden = (const float*)d_in[0];
    const float* Wq = (const float*)d_in[1];
    const float* bq = (const float*)d_in[2];
    const float* Wk = (const float*)d_in[3];
    const float* bk = (const float*)d_in[4];
    const float* Wv = (const float*)d_in[5];
    const float* bv = (const float*)d_in[6];
    const float* Wo = (const float*)d_in[7];
    const float* bo = (const float*)d_in[8];
    float* out = (float*)d_out;

    __half *hh, *hl, *wxh, *wxl, *woh, *qkv, *aoh, *aol;
    float* bx;
    cudaGetSymbolAddress((void**)&hh,  g_hh);
    cudaGetSymbolAddress((void**)&hl,  g_hl);
    cudaGetSymbolAddress((void**)&wxh, g_wxh);
    cudaGetSymbolAddress((void**)&wxl, g_wxl);
    cudaGetSymbolAddress((void**)&woh, g_woh);
    cudaGetSymbolAddress((void**)&bx,  g_bx);
    cudaGetSymbolAddress((void**)&qkv, g_qkv);
    cudaGetSymbolAddress((void**)&aoh, g_aoh);
    cudaGetSymbolAddress((void**)&aol, g_aol);

    // ---- prep ----
    split_hl<<<(MROWS * HIDN / 4 + 255) / 256, 256>>>(hidden, hh, hl, MROWS * HIDN / 4);
    transpose_qkv<<<dim3(QKVN / 32, HIDN / 32), 256>>>(Wq, Wk, Wv, bq, bk, bv,
                                                       wxh, wxl, bx);
    transpose_hi<<<dim3(HIDN / 32, HIDN / 32), 256>>>(Wo, woh, HIDN, HIDN);

    // ---- GEMMs (both 2-term, GBK=64) ----
    const int smemG = 2 * STAGE * sizeof(__half);   // 110592 B
    cudaFuncSetAttribute(gemm_cp<true>,
        cudaFuncAttributeMaxDynamicSharedMemorySize, smemG);
    cudaFuncSetAttribute(gemm_cp<false>,
        cudaFuncAttributeMaxDynamicSharedMemorySize, smemG);

    // fused QKV projection (fp16 out, Q cols scaled 0.125)
    gemm_cp<true><<<dim3(QKVN / 128, MROWS / 128), 256, smemG>>>(
        hh, hl, wxh, bx, qkv, QKVN, HIDN, HIDN);

    // ---- attention ----
    attn_fp16<<<dim3(SEQ / ATQ, NH, BATCH), 256>>>(qkv, aoh, aol);

    // ---- output projection: (aoh+aol) @ Wo_hi + bo (fp32 out) ----
    gemm_cp<false><<<dim3(HIDN / 128, MROWS / 128), 256, smemG>>>(
        aoh, aol, woh, bo, out, HIDN, HIDN, 0);
}

// round 9
// speedup vs baseline: 9.9689x; 1.1966x over previous
#include <cuda_runtime.h>
#include <cuda_fp16.h>
#include <cstdint>
#include <math.h>

// ---------------- problem constants ----------------
#define BATCH 2
#define SEQ   2048
#define HIDN  2048
#define NH    32
#define NG    8
#define HD    64
#define KVD   512
#define QKVN  (HIDN + 2 * KVD)   // 3072
#define MROWS (BATCH*SEQ)        // 4096

// ---------------- device-global scratch ----------------
__device__ __half g_hh  [MROWS * HIDN];
__device__ __half g_wxh [QKVN * HIDN];    // [Wq|Wk|Wv]^T hi  [N=3072][K=2048]
__device__ __half g_woh [HIDN * HIDN];
__device__ float  g_bx  [QKVN];
__device__ __half g_qkv [MROWS * QKVN];   // fused q|k|v (q pre-scaled)
__device__ __half g_aoh [MROWS * HIDN];
__device__ __half g_aol [MROWS * HIDN];

// ---------------- helpers ----------------
__device__ __forceinline__ unsigned sptr(const void* p) {
    return (unsigned)__cvta_generic_to_shared(p);
}
__device__ __forceinline__ void cpa16(unsigned dst, const void* src) {
    asm volatile("cp.async.cg.shared.global [%0], [%1], 16;"
        :: "r"(dst), "l"(src) : "memory");
}
__device__ __forceinline__ void cpa_commit() {
    asm volatile("cp.async.commit_group;" ::: "memory");
}
__device__ __forceinline__ void cpa_wait0() {
    asm volatile("cp.async.wait_group 0;" ::: "memory");
}
__device__ __forceinline__ void ldm_x4(unsigned* r, unsigned a) {
    asm volatile("ldmatrix.sync.aligned.m8n8.x4.shared.b16 {%0,%1,%2,%3}, [%4];"
        : "=r"(r[0]), "=r"(r[1]), "=r"(r[2]), "=r"(r[3]) : "r"(a));
}
__device__ __forceinline__ void ldm_x4_t(unsigned* r, unsigned a) {
    asm volatile("ldmatrix.sync.aligned.m8n8.x4.trans.shared.b16 {%0,%1,%2,%3}, [%4];"
        : "=r"(r[0]), "=r"(r[1]), "=r"(r[2]), "=r"(r[3]) : "r"(a));
}
__device__ __forceinline__ void mma16(float* c, const unsigned* a, const unsigned* b) {
    asm volatile(
        "mma.sync.aligned.m16n8k16.row.col.f32.f16.f16.f32 "
        "{%0,%1,%2,%3}, {%4,%5,%6,%7}, {%8,%9}, {%0,%1,%2,%3};"
        : "+f"(c[0]), "+f"(c[1]), "+f"(c[2]), "+f"(c[3])
        : "r"(a[0]), "r"(a[1]), "r"(a[2]), "r"(a[3]), "r"(b[0]), "r"(b[1]));
}
__device__ __forceinline__ unsigned packh2(float x, float y) {
    __half2 h = __floats2half2_rn(x, y);
    return *(unsigned*)&h;
}

// ===================== prep: fp32 -> fp16 convert ============================
__global__ __launch_bounds__(256) void convert_h(
    const float* __restrict__ x, __half* __restrict__ hi, int n4)
{
    int i = blockIdx.x * 256 + threadIdx.x;
    if (i >= n4) return;
    float4 v = ((const float4*)x)[i];
    ((__half2*)hi)[2*i]   = __floats2half2_rn(v.x, v.y);
    ((__half2*)hi)[2*i+1] = __floats2half2_rn(v.z, v.w);
}

// ===================== prep: fused [Wq|Wk|Wv] transpose + bias ===============
__global__ __launch_bounds__(256) void transpose_qkv(
    const float* __restrict__ Wq, const float* __restrict__ Wk,
    const float* __restrict__ Wv,
    const float* __restrict__ bq, const float* __restrict__ bk,
    const float* __restrict__ bv,
    __half* __restrict__ Th, float* __restrict__ bx)
{
    __shared__ float t[32][33];
    const int n0 = blockIdx.x * 32;
    const int k0 = blockIdx.y * 32;
    const int tx = threadIdx.x & 31, ty = threadIdx.x >> 5;

    const float* W;
    const float* bsrc;
    int nsrc, nwid;
    if (n0 < HIDN)            { W = Wq; bsrc = bq; nsrc = n0;              nwid = HIDN; }
    else if (n0 < HIDN + KVD) { W = Wk; bsrc = bk; nsrc = n0 - HIDN;       nwid = KVD;  }
    else                      { W = Wv; bsrc = bv; nsrc = n0 - HIDN - KVD; nwid = KVD;  }

    if (blockIdx.y == 0 && ty == 0)
        bx[n0 + tx] = bsrc[nsrc + tx];

    #pragma unroll
    for (int i = 0; i < 4; i++)
        t[ty + 8*i][tx] = W[(size_t)(k0 + ty + 8*i) * nwid + nsrc + tx];
    __syncthreads();
    #pragma unroll
    for (int i = 0; i < 4; i++)
        Th[(size_t)(n0 + ty + 8*i) * HIDN + k0 + tx] = __float2half_rn(t[tx][ty + 8*i]);
}

// ===================== prep: Wo transpose (hi only) ==========================
__global__ __launch_bounds__(256) void transpose_hi(
    const float* __restrict__ W, __half* __restrict__ Th, int K, int N)
{
    __shared__ float t[32][33];
    const int n0 = blockIdx.x * 32, k0 = blockIdx.y * 32;
    const int tx = threadIdx.x & 31, ty = threadIdx.x >> 5;
    #pragma unroll
    for (int i = 0; i < 4; i++)
        t[ty + 8*i][tx] = W[(size_t)(k0 + ty + 8*i) * N + n0 + tx];
    __syncthreads();
    #pragma unroll
    for (int i = 0; i < 4; i++)
        Th[(size_t)(n0 + ty + 8*i) * K + k0 + tx] = __float2half_rn(t[tx][ty + 8*i]);
}

// ===================== GEMM (1- or 2-term A), cp.async, GBK=64 ===============
#define GBK   64
#define KSTRH 72                         // 64 + 8 pad halves (144 B row)
#define MATH  (128 * KSTRH)              // 9216 halves per matrix tile

template<int TERMS, bool HALF_OUT>       // TERMS: A matrices (1 = Ah, 2 = Ah+Al)
__global__ __launch_bounds__(256) void gemm_cp(
    const __half* __restrict__ Ah, const __half* __restrict__ Al,
    const __half* __restrict__ Bh,
    const float* __restrict__ bias, void* __restrict__ Cout,
    int N, int K, int qcols)             // cols < qcols get 0.125 scale
{
    constexpr int NMAT  = TERMS + 1;
    constexpr int STAGE = NMAT * MATH;
    extern __shared__ __half smh[];

    const int tid = threadIdx.x;
    const int wid = tid >> 5, lane = tid & 31;
    const int gid = lane >> 2, tig = lane & 3;
    const int wm = wid >> 1, wn = wid & 1;
    const int rowBase = blockIdx.y * 128;
    const int colBase = blockIdx.x * 128;

    float acc[2][8][4];
    #pragma unroll
    for (int mt = 0; mt < 2; mt++)
        #pragma unroll
        for (int nt = 0; nt < 8; nt++)
            #pragma unroll
            for (int e = 0; e < 4; e++) acc[mt][nt][e] = 0.f;

    const int aRow = wm * 32 + (lane & 15);
    const int aColSel = (lane >> 4) * 8;
    const int bRowSel = ((lane >> 4) & 1) * 8 + (lane & 7);
    const int bColSel = ((lane >> 3) & 1) * 8;

    auto load_stage = [&](int kb, int ib) {
        unsigned base = sptr(smh) + (unsigned)(ib * STAGE) * 2;
        size_t ka = (size_t)kb * GBK;
        #pragma unroll
        for (int i = 0; i < 4; i++) {
            int f = i * 256 + tid;           // 1024 chunks per matrix
            int r = f >> 3, c = (f & 7) * 8;
            unsigned soff = base + (unsigned)(r * KSTRH + c) * 2;
            size_t ga = (size_t)(rowBase + r) * K + ka + c;
            size_t gb = (size_t)(colBase + r) * K + ka + c;
            cpa16(soff, Ah + ga);
            if (TERMS == 2) cpa16(soff + MATH * 2, Al + ga);
            cpa16(soff + (NMAT - 1) * MATH * 2, Bh + gb);
        }
    };

    const int kblocks = K / GBK;
    load_stage(0, 0);
    cpa_commit();

    for (int kb = 0; kb < kblocks; kb++) {
        const int ib = kb & 1;
        cpa_wait0();
        __syncthreads();
        if (kb + 1 < kblocks) {
            load_stage(kb + 1, ib ^ 1);
            cpa_commit();
        }

        const __half* As = smh + ib * STAGE;
        const __half* Bs = As + (NMAT - 1) * MATH;

        #pragma unroll
        for (int ks = 0; ks < 4; ks++) {
            const int kk = ks * 16;
            unsigned ah[2][4], al[2][4];
            #pragma unroll
            for (int mt = 0; mt < 2; mt++) {
                int off = (aRow + mt * 16) * KSTRH + kk + aColSel;
                ldm_x4(ah[mt], sptr(As + off));
                if (TERMS == 2) ldm_x4(al[mt], sptr(As + MATH + off));
            }
            #pragma unroll
            for (int np = 0; np < 4; np++) {
                int off = (wn * 64 + np * 16 + bRowSel) * KSTRH + kk + bColSel;
                unsigned bh[4];
                ldm_x4(bh, sptr(Bs + off));
                #pragma unroll
                for (int mt = 0; mt < 2; mt++) {
                    mma16(acc[mt][np*2+0], ah[mt], bh + 0);
                    mma16(acc[mt][np*2+1], ah[mt], bh + 2);
                    if (TERMS == 2) {
                        mma16(acc[mt][np*2+0], al[mt], bh + 0);
                        mma16(acc[mt][np*2+1], al[mt], bh + 2);
                    }
                }
            }
        }
    }

    #pragma unroll
    for (int mt = 0; mt < 2; mt++) {
        int r0 = rowBase + wm * 32 + mt * 16 + gid;
        #pragma unroll
        for (int nt = 0; nt < 8; nt++) {
            int c = colBase + wn * 64 + nt * 8 + tig * 2;
            float sc = (c < qcols) ? 0.125f : 1.0f;
            float2 bb = *(const float2*)(bias + c);
            float v0 = (acc[mt][nt][0] + bb.x) * sc;
            float v1 = (acc[mt][nt][1] + bb.y) * sc;
            float v2 = (acc[mt][nt][2] + bb.x) * sc;
            float v3 = (acc[mt][nt][3] + bb.y) * sc;
            if (HALF_OUT) {
                __half* C = (__half*)Cout;
                *(__half2*)(C + (size_t)r0 * N + c)       = __floats2half2_rn(v0, v1);
                *(__half2*)(C + (size_t)(r0 + 8) * N + c) = __floats2half2_rn(v2, v3);
            } else {
                float* C = (float*)Cout;
                *(float2*)(C + (size_t)r0 * N + c)       = make_float2(v0, v1);
                *(float2*)(C + (size_t)(r0 + 8) * N + c) = make_float2(v2, v3);
            }
        }
    }
}

// ===================== Flash attention (fp16 MMA, cp.async K/V pipeline) =====
#define ATQ  128
#define AKT  64
#define KSTR 72

__global__ __launch_bounds__(256, 2) void attn_fp16(
    const __half* __restrict__ QKV, __half* __restrict__ Oh, __half* __restrict__ Ol)
{
    __shared__ __half Ks[2][AKT * KSTR];
    __shared__ __half Vs[2][AKT * KSTR];

    const int qt = blockIdx.x, h = blockIdx.y, b = blockIdx.z;
    const int g = h >> 2;
    const int tid = threadIdx.x, wid = tid >> 5, lane = tid & 31;
    const int gid = lane >> 2, tig = lane & 3;
    const int qrow0 = qt * ATQ + wid * 16;

    const __half* Kbase = QKV + HIDN + (size_t)g * HD;
    const __half* Vbase = QKV + HIDN + KVD + (size_t)g * HD;

    const int lr0 = tid >> 2;
    auto load_tile = [&](int kt, int ib) {
        #pragma unroll
        for (int i = 0; i < 2; i++) {
            int r = lr0;
            int cc = (tid & 3) * 16 + i * 8;
            size_t gb = (size_t)(b * SEQ + kt * AKT + r) * QKVN + cc;
            cpa16(sptr(&Ks[ib][r * KSTR + cc]), Kbase + gb);
            cpa16(sptr(&Vs[ib][r * KSTR + cc]), Vbase + gb);
        }
    };

    unsigned qf[4][4];
    {
        const __half* qb = QKV + (size_t)(b * SEQ + qrow0) * QKVN + h * HD;
        #pragma unroll
        for (int ks = 0; ks < 4; ks++)
            #pragma unroll
            for (int e = 0; e < 4; e++) {
                int rr = gid + (e & 1) * 8;
                int cc = ks * 16 + tig * 2 + (e >> 1) * 8;
                qf[ks][e] = *(const unsigned*)(qb + (size_t)rr * QKVN + cc);
            }
    }

    load_tile(0, 0);
    cpa_commit();

    float o[8][4];
    #pragma unroll
    for (int nt = 0; nt < 8; nt++)
        #pragma unroll
        for (int e = 0; e < 4; e++) o[nt][e] = 0.f;
    float m0 = -INFINITY, m1 = -INFINITY, l0 = 0.f, l1 = 0.f;

    const int kRowSel = ((lane >> 4) & 1) * 8 + (lane & 7);
    const int kColSel = ((lane >> 3) & 1) * 8;
    const int vRowSel = ((lane >> 3) & 1) * 8 + (lane & 7);
    const int vColSel = ((lane >> 4) & 1) * 8;

    const int NT = SEQ / AKT;
    for (int kt = 0; kt < NT; kt++) {
        const int ib = kt & 1;
        cpa_wait0();
        __syncthreads();
        if (kt + 1 < NT) {
            load_tile(kt + 1, ib ^ 1);
            cpa_commit();
        }

        float sc[8][4];
        #pragma unroll
        for (int nt = 0; nt < 8; nt++)
            #pragma unroll
            for (int e = 0; e < 4; e++) sc[nt][e] = 0.f;
        #pragma unroll
        for (int ks = 0; ks < 4; ks++) {
            #pragma unroll
            for (int np = 0; np < 4; np++) {
                unsigned bb[4];
                ldm_x4(bb, sptr(&Ks[ib][(np * 16 + kRowSel) * KSTR + ks * 16 + kColSel]));
                mma16(sc[np*2+0], qf[ks], bb + 0);
                mma16(sc[np*2+1], qf[ks], bb + 2);
            }
        }

        float mx0 = -INFINITY, mx1 = -INFINITY;
        #pragma unroll
        for (int nt = 0; nt < 8; nt++) {
            mx0 = fmaxf(mx0, fmaxf(sc[nt][0], sc[nt][1]));
            mx1 = fmaxf(mx1, fmaxf(sc[nt][2], sc[nt][3]));
        }
        mx0 = fmaxf(mx0, __shfl_xor_sync(0xffffffffu, mx0, 1));
        mx0 = fmaxf(mx0, __shfl_xor_sync(0xffffffffu, mx0, 2));
        mx1 = fmaxf(mx1, __shfl_xor_sync(0xffffffffu, mx1, 1));
        mx1 = fmaxf(mx1, __shfl_xor_sync(0xffffffffu, mx1, 2));

        float mn0 = fmaxf(m0, mx0), mn1 = fmaxf(m1, mx1);
        float al0 = __expf(m0 - mn0), al1 = __expf(m1 - mn1);
        unsigned pf[4][4];
        float s0 = 0.f, s1 = 0.f;
        #pragma unroll
        for (int nt = 0; nt < 8; nt++) {
            float p0 = __expf(sc[nt][0] - mn0);
            float p1 = __expf(sc[nt][1] - mn0);
            float p2 = __expf(sc[nt][2] - mn1);
            float p3 = __expf(sc[nt][3] - mn1);
            s0 += p0 + p1;  s1 += p2 + p3;
            int ks = nt >> 1, hiSel = (nt & 1) * 2;
            pf[ks][0 + hiSel] = packh2(p0, p1);
            pf[ks][1 + hiSel] = packh2(p2, p3);
        }
        s0 += __shfl_xor_sync(0xffffffffu, s0, 1);
        s0 += __shfl_xor_sync(0xffffffffu, s0, 2);
        s1 += __shfl_xor_sync(0xffffffffu, s1, 1);
        s1 += __shfl_xor_sync(0xffffffffu, s1, 2);
        l0 = l0 * al0 + s0;  m0 = mn0;
        l1 = l1 * al1 + s1;  m1 = mn1;
        #pragma unroll
        for (int nt = 0; nt < 8; nt++) {
            o[nt][0] *= al0; o[nt][1] *= al0;
            o[nt][2] *= al1; o[nt][3] *= al1;
        }

        #pragma unroll
        for (int ks = 0; ks < 4; ks++) {
            #pragma unroll
            for (int np = 0; np < 4; np++) {
                unsigned bb[4];
                ldm_x4_t(bb, sptr(&Vs[ib][(ks * 16 + vRowSel) * KSTR + np * 16 + vColSel]));
                mma16(o[np*2+0], pf[ks], bb + 0);
                mma16(o[np*2+1], pf[ks], bb + 2);
            }
        }
    }

    float i0 = 1.f / l0, i1 = 1.f / l1;
    size_t r0 = (size_t)(b * SEQ + qrow0 + gid);
    __half* d0h = Oh + r0 * HIDN + h * HD;
    __half* d0l = Ol + r0 * HIDN + h * HD;
    __half* d1h = d0h + (size_t)8 * HIDN;
    __half* d1l = d0l + (size_t)8 * HIDN;
    #pragma unroll
    for (int nt = 0; nt < 8; nt++) {
        int c = nt * 8 + tig * 2;
        float x0 = o[nt][0] * i0, y0 = o[nt][1] * i0;
        float x1 = o[nt][2] * i1, y1 = o[nt][3] * i1;
        __half hx0 = __float2half_rn(x0), hy0 = __float2half_rn(y0);
        __half hx1 = __float2half_rn(x1), hy1 = __float2half_rn(y1);
        *(__half2*)(d0h + c) = __halves2half2(hx0, hy0);
        *(__half2*)(d1h + c) = __halves2half2(hx1, hy1);
        *(__half2*)(d0l + c) = __halves2half2(
            __float2half_rn(x0 - __half2float(hx0)), __float2half_rn(y0 - __half2float(hy0)));
        *(__half2*)(d1l + c) = __halves2half2(
            __float2half_rn(x1 - __half2float(hx1)), __float2half_rn(y1 - __half2float(hy1)));
    }
}

// ===================== launch =====================
extern "C" void kernel_launch(void* const* d_in, const int* in_sizes, int n_in,
                              void* d_out, int out_size)
{
    const float* hidden = (const float*)d_in[0];
    const float* Wq = (const float*)d_in[1];
    const float* bq = (const float*)d_in[2];
    const float* Wk = (const float*)d_in[3];
    const float* bk = (const float*)d_in[4];
    const float* Wv = (const float*)d_in[5];
    const float* bv = (const float*)d_in[6];
    const float* Wo = (const float*)d_in[7];
    const float* bo = (const float*)d_in[8];
    float* out = (float*)d_out;

    __half *hh, *wxh, *woh, *qkv, *aoh, *aol;
    float* bx;
    cudaGetSymbolAddress((void**)&hh,  g_hh);
    cudaGetSymbolAddress((void**)&wxh, g_wxh);
    cudaGetSymbolAddress((void**)&woh, g_woh);
    cudaGetSymbolAddress((void**)&bx,  g_bx);
    cudaGetSymbolAddress((void**)&qkv, g_qkv);
    cudaGetSymbolAddress((void**)&aoh, g_aoh);
    cudaGetSymbolAddress((void**)&aol, g_aol);

    // ---- prep ----
    convert_h<<<(MROWS * HIDN / 4 + 255) / 256, 256>>>(hidden, hh, MROWS * HIDN / 4);
    transpose_qkv<<<dim3(QKVN / 32, HIDN / 32), 256>>>(Wq, Wk, Wv, bq, bk, bv,
                                                       wxh, bx);
    transpose_hi<<<dim3(HIDN / 32, HIDN / 32), 256>>>(Wo, woh, HIDN, HIDN);

    // ---- GEMMs ----
    const int smemQ = 2 * 2 * MATH * sizeof(__half);   // 73728 (1-term)
    const int smemO = 2 * 3 * MATH * sizeof(__half);   // 110592 (2-term)
    cudaFuncSetAttribute(gemm_cp<1, true>,
        cudaFuncAttributeMaxDynamicSharedMemorySize, smemQ);
    cudaFuncSetAttribute(gemm_cp<2, false>,
        cudaFuncAttributeMaxDynamicSharedMemorySize, smemO);

    // fused QKV projection: 1-term (hh @ Wx_hi), fp16 out, Q cols scaled 0.125
    gemm_cp<1, true><<<dim3(QKVN / 128, MROWS / 128), 256, smemQ>>>(
        hh, nullptr, wxh, bx, qkv, QKVN, HIDN, HIDN);

    // ---- attention ----
    attn_fp16<<<dim3(SEQ / ATQ, NH, BATCH), 256>>>(qkv, aoh, aol);

    // ---- output projection: (aoh+aol) @ Wo_hi + bo (fp32 out) ----
    gemm_cp<2, false><<<dim3(HIDN / 128, MROWS / 128), 256, smemO>>>(
        aoh, aol, woh, bo, out, HIDN, HIDN, 0);
}

// round 10
// speedup vs baseline: 11.8092x; 1.1846x over previous
#include <cuda_runtime.h>
#include <cuda_fp16.h>
#include <cstdint>
#include <math.h>

// ---------------- problem constants ----------------
#define BATCH 2
#define SEQ   2048
#define HIDN  2048
#define NH    32
#define NG    8
#define HD    64
#define KVD   512
#define QKVN  (HIDN + 2 * KVD)   // 3072
#define MROWS (BATCH*SEQ)        // 4096

// Q pre-scale: (1/sqrt(64)) * log2(e)  -> softmax uses ex2 directly
#define QSCALE 0.18033688f

// ---------------- device-global scratch ----------------
__device__ __half g_hh  [MROWS * HIDN];
__device__ __half g_wxh [QKVN * HIDN];    // [Wq|Wk|Wv]^T hi  [N=3072][K=2048]
__device__ __half g_woh [HIDN * HIDN];
__device__ float  g_bx  [QKVN];
__device__ __half g_qkv [MROWS * QKVN];   // fused q|k|v (q pre-scaled)
__device__ __half g_aoh [MROWS * HIDN];

// ---------------- helpers ----------------
__device__ __forceinline__ unsigned sptr(const void* p) {
    return (unsigned)__cvta_generic_to_shared(p);
}
__device__ __forceinline__ void cpa16(unsigned dst, const void* src) {
    asm volatile("cp.async.cg.shared.global [%0], [%1], 16;"
        :: "r"(dst), "l"(src) : "memory");
}
__device__ __forceinline__ void cpa_commit() {
    asm volatile("cp.async.commit_group;" ::: "memory");
}
__device__ __forceinline__ void cpa_wait0() {
    asm volatile("cp.async.wait_group 0;" ::: "memory");
}
__device__ __forceinline__ void ldm_x4(unsigned* r, unsigned a) {
    asm volatile("ldmatrix.sync.aligned.m8n8.x4.shared.b16 {%0,%1,%2,%3}, [%4];"
        : "=r"(r[0]), "=r"(r[1]), "=r"(r[2]), "=r"(r[3]) : "r"(a));
}
__device__ __forceinline__ void ldm_x4_t(unsigned* r, unsigned a) {
    asm volatile("ldmatrix.sync.aligned.m8n8.x4.trans.shared.b16 {%0,%1,%2,%3}, [%4];"
        : "=r"(r[0]), "=r"(r[1]), "=r"(r[2]), "=r"(r[3]) : "r"(a));
}
__device__ __forceinline__ void mma16(float* c, const unsigned* a, const unsigned* b) {
    asm volatile(
        "mma.sync.aligned.m16n8k16.row.col.f32.f16.f16.f32 "
        "{%0,%1,%2,%3}, {%4,%5,%6,%7}, {%8,%9}, {%0,%1,%2,%3};"
        : "+f"(c[0]), "+f"(c[1]), "+f"(c[2]), "+f"(c[3])
        : "r"(a[0]), "r"(a[1]), "r"(a[2]), "r"(a[3]), "r"(b[0]), "r"(b[1]));
}
__device__ __forceinline__ float ex2(float x) {
    float r;
    asm("ex2.approx.f32 %0, %1;" : "=f"(r) : "f"(x));
    return r;
}
__device__ __forceinline__ unsigned packh2(float x, float y) {
    __half2 h = __floats2half2_rn(x, y);
    return *(unsigned*)&h;
}

// ===================== prep: fp32 -> fp16 convert ============================
__global__ __launch_bounds__(256) void convert_h(
    const float* __restrict__ x, __half* __restrict__ hi, int n4)
{
    int i = blockIdx.x * 256 + threadIdx.x;
    if (i >= n4) return;
    float4 v = ((const float4*)x)[i];
    ((__half2*)hi)[2*i]   = __floats2half2_rn(v.x, v.y);
    ((__half2*)hi)[2*i+1] = __floats2half2_rn(v.z, v.w);
}

// ===================== prep: fused [Wq|Wk|Wv] transpose + bias ===============
__global__ __launch_bounds__(256) void transpose_qkv(
    const float* __restrict__ Wq, const float* __restrict__ Wk,
    const float* __restrict__ Wv,
    const float* __restrict__ bq, const float* __restrict__ bk,
    const float* __restrict__ bv,
    __half* __restrict__ Th, float* __restrict__ bx)
{
    __shared__ float t[32][33];
    const int n0 = blockIdx.x * 32;
    const int k0 = blockIdx.y * 32;
    const int tx = threadIdx.x & 31, ty = threadIdx.x >> 5;

    const float* W;
    const float* bsrc;
    int nsrc, nwid;
    if (n0 < HIDN)            { W = Wq; bsrc = bq; nsrc = n0;              nwid = HIDN; }
    else if (n0 < HIDN + KVD) { W = Wk; bsrc = bk; nsrc = n0 - HIDN;       nwid = KVD;  }
    else                      { W = Wv; bsrc = bv; nsrc = n0 - HIDN - KVD; nwid = KVD;  }

    if (blockIdx.y == 0 && ty == 0)
        bx[n0 + tx] = bsrc[nsrc + tx];

    #pragma unroll
    for (int i = 0; i < 4; i++)
        t[ty + 8*i][tx] = W[(size_t)(k0 + ty + 8*i) * nwid + nsrc + tx];
    __syncthreads();
    #pragma unroll
    for (int i = 0; i < 4; i++)
        Th[(size_t)(n0 + ty + 8*i) * HIDN + k0 + tx] = __float2half_rn(t[tx][ty + 8*i]);
}

// ===================== prep: Wo transpose (hi only) ==========================
__global__ __launch_bounds__(256) void transpose_hi(
    const float* __restrict__ W, __half* __restrict__ Th, int K, int N)
{
    __shared__ float t[32][33];
    const int n0 = blockIdx.x * 32, k0 = blockIdx.y * 32;
    const int tx = threadIdx.x & 31, ty = threadIdx.x >> 5;
    #pragma unroll
    for (int i = 0; i < 4; i++)
        t[ty + 8*i][tx] = W[(size_t)(k0 + ty + 8*i) * N + n0 + tx];
    __syncthreads();
    #pragma unroll
    for (int i = 0; i < 4; i++)
        Th[(size_t)(n0 + ty + 8*i) * K + k0 + tx] = __float2half_rn(t[tx][ty + 8*i]);
}

// ===================== GEMM (1-term), cp.async, GBK=64 =======================
#define GBK   64
#define KSTRH 72                         // 64 + 8 pad halves (144 B row)
#define MATH  (128 * KSTRH)              // 9216 halves per matrix tile
#define STAGE (2 * MATH)                 // A, B

template<bool HALF_OUT>
__global__ __launch_bounds__(256) void gemm_cp(
    const __half* __restrict__ Ah, const __half* __restrict__ Bh,
    const float* __restrict__ bias, void* __restrict__ Cout,
    int N, int K, int qcols)             // cols < qcols get QSCALE
{
    extern __shared__ __half smh[];

    const int tid = threadIdx.x;
    const int wid = tid >> 5, lane = tid & 31;
    const int gid = lane >> 2, tig = lane & 3;
    const int wm = wid >> 1, wn = wid & 1;
    const int rowBase = blockIdx.y * 128;
    const int colBase = blockIdx.x * 128;

    float acc[2][8][4];
    #pragma unroll
    for (int mt = 0; mt < 2; mt++)
        #pragma unroll
        for (int nt = 0; nt < 8; nt++)
            #pragma unroll
            for (int e = 0; e < 4; e++) acc[mt][nt][e] = 0.f;

    const int aRow = wm * 32 + (lane & 15);
    const int aColSel = (lane >> 4) * 8;
    const int bRowSel = ((lane >> 4) & 1) * 8 + (lane & 7);
    const int bColSel = ((lane >> 3) & 1) * 8;

    auto load_stage = [&](int kb, int ib) {
        unsigned base = sptr(smh) + (unsigned)(ib * STAGE) * 2;
        size_t ka = (size_t)kb * GBK;
        #pragma unroll
        for (int i = 0; i < 4; i++) {
            int f = i * 256 + tid;           // 1024 chunks per matrix
            int r = f >> 3, c = (f & 7) * 8;
            unsigned soff = base + (unsigned)(r * KSTRH + c) * 2;
            cpa16(soff,            Ah + (size_t)(rowBase + r) * K + ka + c);
            cpa16(soff + MATH * 2, Bh + (size_t)(colBase + r) * K + ka + c);
        }
    };

    const int kblocks = K / GBK;
    load_stage(0, 0);
    cpa_commit();

    for (int kb = 0; kb < kblocks; kb++) {
        const int ib = kb & 1;
        cpa_wait0();
        __syncthreads();
        if (kb + 1 < kblocks) {
            load_stage(kb + 1, ib ^ 1);
            cpa_commit();
        }

        const __half* As = smh + ib * STAGE;
        const __half* Bs = As + MATH;

        #pragma unroll
        for (int ks = 0; ks < 4; ks++) {
            const int kk = ks * 16;
            unsigned ah[2][4];
            #pragma unroll
            for (int mt = 0; mt < 2; mt++)
                ldm_x4(ah[mt], sptr(As + (aRow + mt * 16) * KSTRH + kk + aColSel));
            #pragma unroll
            for (int np = 0; np < 4; np++) {
                unsigned bh[4];
                ldm_x4(bh, sptr(Bs + (wn * 64 + np * 16 + bRowSel) * KSTRH + kk + bColSel));
                #pragma unroll
                for (int mt = 0; mt < 2; mt++) {
                    mma16(acc[mt][np*2+0], ah[mt], bh + 0);
                    mma16(acc[mt][np*2+1], ah[mt], bh + 2);
                }
            }
        }
    }

    #pragma unroll
    for (int mt = 0; mt < 2; mt++) {
        int r0 = rowBase + wm * 32 + mt * 16 + gid;
        #pragma unroll
        for (int nt = 0; nt < 8; nt++) {
            int c = colBase + wn * 64 + nt * 8 + tig * 2;
            float sc = (c < qcols) ? QSCALE : 1.0f;
            float2 bb = *(const float2*)(bias + c);
            float v0 = (acc[mt][nt][0] + bb.x) * sc;
            float v1 = (acc[mt][nt][1] + bb.y) * sc;
            float v2 = (acc[mt][nt][2] + bb.x) * sc;
            float v3 = (acc[mt][nt][3] + bb.y) * sc;
            if (HALF_OUT) {
                __half* C = (__half*)Cout;
                *(__half2*)(C + (size_t)r0 * N + c)       = __floats2half2_rn(v0, v1);
                *(__half2*)(C + (size_t)(r0 + 8) * N + c) = __floats2half2_rn(v2, v3);
            } else {
                float* C = (float*)Cout;
                *(float2*)(C + (size_t)r0 * N + c)       = make_float2(v0, v1);
                *(float2*)(C + (size_t)(r0 + 8) * N + c) = make_float2(v2, v3);
            }
        }
    }
}

// ===================== Flash attention (fp16 MMA, base-2 softmax) ============
#define ATQ  128
#define AKT  64
#define KSTR 72

__global__ __launch_bounds__(256, 2) void attn_fp16(
    const __half* __restrict__ QKV, __half* __restrict__ Oh)
{
    __shared__ __half Ks[2][AKT * KSTR];
    __shared__ __half Vs[2][AKT * KSTR];

    const int qt = blockIdx.x, h = blockIdx.y, b = blockIdx.z;
    const int g = h >> 2;
    const int tid = threadIdx.x, wid = tid >> 5, lane = tid & 31;
    const int gid = lane >> 2, tig = lane & 3;
    const int qrow0 = qt * ATQ + wid * 16;

    const __half* Kbase = QKV + HIDN + (size_t)g * HD;
    const __half* Vbase = QKV + HIDN + KVD + (size_t)g * HD;

    const int lr0 = tid >> 2;
    auto load_tile = [&](int kt, int ib) {
        #pragma unroll
        for (int i = 0; i < 2; i++) {
            int r = lr0;
            int cc = (tid & 3) * 16 + i * 8;
            size_t gb = (size_t)(b * SEQ + kt * AKT + r) * QKVN + cc;
            cpa16(sptr(&Ks[ib][r * KSTR + cc]), Kbase + gb);
            cpa16(sptr(&Vs[ib][r * KSTR + cc]), Vbase + gb);
        }
    };

    unsigned qf[4][4];
    {
        const __half* qb = QKV + (size_t)(b * SEQ + qrow0) * QKVN + h * HD;
        #pragma unroll
        for (int ks = 0; ks < 4; ks++)
            #pragma unroll
            for (int e = 0; e < 4; e++) {
                int rr = gid + (e & 1) * 8;
                int cc = ks * 16 + tig * 2 + (e >> 1) * 8;
                qf[ks][e] = *(const unsigned*)(qb + (size_t)rr * QKVN + cc);
            }
    }

    load_tile(0, 0);
    cpa_commit();

    float o[8][4];
    #pragma unroll
    for (int nt = 0; nt < 8; nt++)
        #pragma unroll
        for (int e = 0; e < 4; e++) o[nt][e] = 0.f;
    float m0 = -INFINITY, m1 = -INFINITY, l0 = 0.f, l1 = 0.f;

    const int kRowSel = ((lane >> 4) & 1) * 8 + (lane & 7);
    const int kColSel = ((lane >> 3) & 1) * 8;
    const int vRowSel = ((lane >> 3) & 1) * 8 + (lane & 7);
    const int vColSel = ((lane >> 4) & 1) * 8;

    const int NT = SEQ / AKT;
    for (int kt = 0; kt < NT; kt++) {
        const int ib = kt & 1;
        cpa_wait0();
        __syncthreads();
        if (kt + 1 < NT) {
            load_tile(kt + 1, ib ^ 1);
            cpa_commit();
        }

        float sc[8][4];
        #pragma unroll
        for (int nt = 0; nt < 8; nt++)
            #pragma unroll
            for (int e = 0; e < 4; e++) sc[nt][e] = 0.f;
        #pragma unroll
        for (int ks = 0; ks < 4; ks++) {
            #pragma unroll
            for (int np = 0; np < 4; np++) {
                unsigned bb[4];
                ldm_x4(bb, sptr(&Ks[ib][(np * 16 + kRowSel) * KSTR + ks * 16 + kColSel]));
                mma16(sc[np*2+0], qf[ks], bb + 0);
                mma16(sc[np*2+1], qf[ks], bb + 2);
            }
        }

        float mx0 = -INFINITY, mx1 = -INFINITY;
        #pragma unroll
        for (int nt = 0; nt < 8; nt++) {
            mx0 = fmaxf(mx0, fmaxf(sc[nt][0], sc[nt][1]));
            mx1 = fmaxf(mx1, fmaxf(sc[nt][2], sc[nt][3]));
        }
        mx0 = fmaxf(mx0, __shfl_xor_sync(0xffffffffu, mx0, 1));
        mx0 = fmaxf(mx0, __shfl_xor_sync(0xffffffffu, mx0, 2));
        mx1 = fmaxf(mx1, __shfl_xor_sync(0xffffffffu, mx1, 1));
        mx1 = fmaxf(mx1, __shfl_xor_sync(0xffffffffu, mx1, 2));

        float mn0 = fmaxf(m0, mx0), mn1 = fmaxf(m1, mx1);
        float al0 = ex2(m0 - mn0), al1 = ex2(m1 - mn1);
        unsigned pf[4][4];
        float s0 = 0.f, s1 = 0.f;
        #pragma unroll
        for (int nt = 0; nt < 8; nt++) {
            float p0 = ex2(sc[nt][0] - mn0);
            float p1 = ex2(sc[nt][1] - mn0);
            float p2 = ex2(sc[nt][2] - mn1);
            float p3 = ex2(sc[nt][3] - mn1);
            s0 += p0 + p1;  s1 += p2 + p3;
            int ks = nt >> 1, hiSel = (nt & 1) * 2;
            pf[ks][0 + hiSel] = packh2(p0, p1);
            pf[ks][1 + hiSel] = packh2(p2, p3);
        }
        s0 += __shfl_xor_sync(0xffffffffu, s0, 1);
        s0 += __shfl_xor_sync(0xffffffffu, s0, 2);
        s1 += __shfl_xor_sync(0xffffffffu, s1, 1);
        s1 += __shfl_xor_sync(0xffffffffu, s1, 2);
        l0 = l0 * al0 + s0;  m0 = mn0;
        l1 = l1 * al1 + s1;  m1 = mn1;
        #pragma unroll
        for (int nt = 0; nt < 8; nt++) {
            o[nt][0] *= al0; o[nt][1] *= al0;
            o[nt][2] *= al1; o[nt][3] *= al1;
        }

        #pragma unroll
        for (int ks = 0; ks < 4; ks++) {
            #pragma unroll
            for (int np = 0; np < 4; np++) {
                unsigned bb[4];
                ldm_x4_t(bb, sptr(&Vs[ib][(ks * 16 + vRowSel) * KSTR + np * 16 + vColSel]));
                mma16(o[np*2+0], pf[ks], bb + 0);
                mma16(o[np*2+1], pf[ks], bb + 2);
            }
        }
    }

    float i0 = 1.f / l0, i1 = 1.f / l1;
    size_t r0 = (size_t)(b * SEQ + qrow0 + gid);
    __half* d0 = Oh + r0 * HIDN + h * HD;
    __half* d1 = d0 + (size_t)8 * HIDN;
    #pragma unroll
    for (int nt = 0; nt < 8; nt++) {
        int c = nt * 8 + tig * 2;
        *(__half2*)(d0 + c) = __floats2half2_rn(o[nt][0] * i0, o[nt][1] * i0);
        *(__half2*)(d1 + c) = __floats2half2_rn(o[nt][2] * i1, o[nt][3] * i1);
    }
}

// ===================== launch =====================
extern "C" void kernel_launch(void* const* d_in, const int* in_sizes, int n_in,
                              void* d_out, int out_size)
{
    const float* hidden = (const float*)d_in[0];
    const float* Wq = (const float*)d_in[1];
    const float* bq = (const float*)d_in[2];
    const float* Wk = (const float*)d_in[3];
    const float* bk = (const float*)d_in[4];
    const float* Wv = (const float*)d_in[5];
    const float* bv = (const float*)d_in[6];
    const float* Wo = (const float*)d_in[7];
    const float* bo = (const float*)d_in[8];
    float* out = (float*)d_out;

    __half *hh, *wxh, *woh, *qkv, *aoh;
    float* bx;
    cudaGetSymbolAddress((void**)&hh,  g_hh);
    cudaGetSymbolAddress((void**)&wxh, g_wxh);
    cudaGetSymbolAddress((void**)&woh, g_woh);
    cudaGetSymbolAddress((void**)&bx,  g_bx);
    cudaGetSymbolAddress((void**)&qkv, g_qkv);
    cudaGetSymbolAddress((void**)&aoh, g_aoh);

    // ---- prep ----
    convert_h<<<(MROWS * HIDN / 4 + 255) / 256, 256>>>(hidden, hh, MROWS * HIDN / 4);
    transpose_qkv<<<dim3(QKVN / 32, HIDN / 32), 256>>>(Wq, Wk, Wv, bq, bk, bv,
                                                       wxh, bx);
    transpose_hi<<<dim3(HIDN / 32, HIDN / 32), 256>>>(Wo, woh, HIDN, HIDN);

    // ---- GEMMs (both 1-term) ----
    const int smemG = 2 * STAGE * sizeof(__half);   // 73728
    cudaFuncSetAttribute(gemm_cp<true>,
        cudaFuncAttributeMaxDynamicSharedMemorySize, smemG);
    cudaFuncSetAttribute(gemm_cp<false>,
        cudaFuncAttributeMaxDynamicSharedMemorySize, smemG);

    // fused QKV projection: fp16 out, Q cols scaled by QSCALE (incl. log2e)
    gemm_cp<true><<<dim3(QKVN / 128, MROWS / 128), 256, smemG>>>(
        hh, wxh, bx, qkv, QKVN, HIDN, HIDN);

    // ---- attention (base-2 softmax) ----
    attn_fp16<<<dim3(SEQ / ATQ, NH, BATCH), 256>>>(qkv, aoh);

    // ---- output projection: aoh @ Wo_hi + bo (fp32 out) ----
    gemm_cp<false><<<dim3(HIDN / 128, MROWS / 128), 256, smemG>>>(
        aoh, woh, bo, out, HIDN, HIDN, 0);
}